// round 5
// baseline (speedup 1.0000x reference)
#include <cuda_runtime.h>
#include <cuda_bf16.h>
#include <cuda_fp16.h>
#include <cstdint>

#define N_OBJn 512
#define C_OBJn 151
#define N_RELn 16384
#define C_RELn 51
#define D_DIM  4096

#define OUT_PREDS  (N_OBJn * C_OBJn)          /* 77312 */
#define OUT_REL    (OUT_PREDS + N_OBJn)       /* 77824 */

// Scratch (device globals — no allocation allowed)
__device__ float g_probsT[C_OBJn * N_OBJn];   // [class][obj]
__device__ float g_maskedT[C_OBJn * N_OBJn];  // [class][obj], class 0 unused
__device__ __align__(16) __half g_Whf[64 * D_DIM];  // W as fp16, rows 51..63 zero

// Fork resources created at static-init time.
struct HxFork {
    cudaStream_t s2;
    cudaEvent_t e1, e2;
    HxFork() {
        cudaStreamCreateWithFlags(&s2, cudaStreamNonBlocking);
        cudaEventCreateWithFlags(&e1, cudaEventDisableTiming);
        cudaEventCreateWithFlags(&e2, cudaEventDisableTiming);
    }
};
static HxFork g_fork;

// ---------------------------------------------------------------------------
// helpers
// ---------------------------------------------------------------------------
__device__ __forceinline__ uint32_t smem_u32(const void* p) {
    uint32_t a;
    asm("{ .reg .u64 t; cvta.to.shared.u64 t, %1; cvt.u32.u64 %0, t; }" : "=r"(a) : "l"(p));
    return a;
}
#define SW128(o) ((o) ^ (((o) >> 3) & 0x70))

__device__ __forceinline__ void ldmx4(uint32_t* r, uint32_t addr) {
    asm volatile("ldmatrix.sync.aligned.m8n8.x4.shared.b16 {%0,%1,%2,%3}, [%4];"
                 : "=r"(r[0]), "=r"(r[1]), "=r"(r[2]), "=r"(r[3]) : "r"(addr));
}
__device__ __forceinline__ void mma_f16(float* d, const uint32_t* a, const uint32_t* b) {
    asm volatile(
        "mma.sync.aligned.m16n8k16.row.col.f32.f16.f16.f32 "
        "{%0,%1,%2,%3},{%4,%5,%6,%7},{%8,%9},{%0,%1,%2,%3};"
        : "+f"(d[0]), "+f"(d[1]), "+f"(d[2]), "+f"(d[3])
        : "r"(a[0]), "r"(a[1]), "r"(a[2]), "r"(a[3]), "r"(b[0]), "r"(b[1]));
}

// ---------------------------------------------------------------------------
// Kernel 1: row softmax (one warp per row) + copy logits to out[0:77312)
// ---------------------------------------------------------------------------
__global__ void softmax_copy_kernel(const float* __restrict__ logits,
                                    float* __restrict__ out)
{
    int warp = threadIdx.x >> 5;
    int lane = threadIdx.x & 31;
    int row  = blockIdx.x * 8 + warp;
    if (row >= N_OBJn) return;

    float v[5];
    float mx = -1e30f;
#pragma unroll
    for (int s = 0; s < 5; s++) {
        int c = lane + 32 * s;
        v[s] = (c < C_OBJn) ? logits[row * C_OBJn + c] : -1e30f;
        mx = fmaxf(mx, v[s]);
    }
#pragma unroll
    for (int o = 16; o; o >>= 1) mx = fmaxf(mx, __shfl_xor_sync(0xffffffffu, mx, o));

    float e[5];
    float sum = 0.f;
#pragma unroll
    for (int s = 0; s < 5; s++) {
        int c = lane + 32 * s;
        e[s] = (c < C_OBJn) ? expf(v[s] - mx) : 0.f;
        sum += e[s];
    }
#pragma unroll
    for (int o = 16; o; o >>= 1) sum += __shfl_xor_sync(0xffffffffu, sum, o);

#pragma unroll
    for (int s = 0; s < 5; s++) {
        int c = lane + 32 * s;
        if (c < C_OBJn) {
            g_probsT[c * N_OBJn + row] = __fdiv_rn(e[s], sum);
            out[row * C_OBJn + c] = v[s];   // obj_dists2 passthrough
        }
    }
}

// ---------------------------------------------------------------------------
// Kernel 2: per-class NMS (bit-exact IoU predicate vs JAX)
// ---------------------------------------------------------------------------
__global__ __launch_bounds__(512) void nms_kernel(const float* __restrict__ boxes)
{
    __shared__ float s_sc[512];
    __shared__ int   s_id[512];
    __shared__ float s_x1[512], s_y1[512], s_x2[512], s_y2[512], s_ar[512];
    __shared__ unsigned s_mask[512 * 16];
    __shared__ unsigned char s_keep[512];

    const int tid = threadIdx.x;
    const int cls = blockIdx.x + 1;

    s_sc[tid] = g_probsT[cls * N_OBJn + tid];
    s_id[tid] = tid;
    __syncthreads();

    for (int k = 2; k <= 512; k <<= 1) {
        for (int j = k >> 1; j > 0; j >>= 1) {
            int ixj = tid ^ j;
            if (ixj > tid) {
                float si = s_sc[tid], sj = s_sc[ixj];
                int   ii = s_id[tid], ij = s_id[ixj];
                bool pre_ji = (sj > si) || (sj == si && ij < ii);
                bool dir = ((tid & k) == 0);
                if (dir ? pre_ji : !pre_ji) {
                    s_sc[tid] = sj; s_sc[ixj] = si;
                    s_id[tid] = ij; s_id[ixj] = ii;
                }
            }
            __syncthreads();
        }
    }

    {
        int o = s_id[tid];
        float4 bx = *(const float4*)&boxes[(o * C_OBJn + cls) * 4];
        s_x1[tid] = bx.x; s_y1[tid] = bx.y; s_x2[tid] = bx.z; s_y2[tid] = bx.w;
        s_ar[tid] = __fmul_rn(bx.z - bx.x + 1.0f, bx.w - bx.y + 1.0f);
    }
    __syncthreads();

    {
        int w = tid >> 5, lane = tid & 31;
        for (int ii = 0; ii < 32; ii++) {
            int i = (w << 5) | ii;
            float xi1 = s_x1[i], yi1 = s_y1[i], xi2 = s_x2[i], yi2 = s_y2[i];
            float ai = s_ar[i];
#pragma unroll 4
            for (int cc = 0; cc < 16; cc++) {
                int jx = (cc << 5) | lane;
                float xx1 = fmaxf(xi1, s_x1[jx]);
                float yy1 = fmaxf(yi1, s_y1[jx]);
                float xx2 = fminf(xi2, s_x2[jx]);
                float yy2 = fminf(yi2, s_y2[jx]);
                float wd = fmaxf(xx2 - xx1 + 1.0f, 0.0f);
                float ht = fmaxf(yy2 - yy1 + 1.0f, 0.0f);
                float inter = __fmul_rn(wd, ht);
                float den = ai + s_ar[jx] - inter;
                unsigned m = __ballot_sync(0xffffffffu, __fdiv_rn(inter, den) > 0.3f);
                if (lane == cc) s_mask[(i << 4) + cc] = m;
            }
        }
    }
    __syncthreads();

    if (tid < 32) {
        int lane = tid;
        unsigned sup = 0;
        for (int i = 0; i < 512; i++) {
            unsigned wi = __shfl_sync(0xffffffffu, sup, i >> 5);
            bool keep = ((wi >> (i & 31)) & 1u) == 0u;
            if (keep && lane < 16) sup |= s_mask[(i << 4) + lane];
            if (lane == 0) s_keep[i] = keep ? 1 : 0;
        }
    }
    __syncthreads();

    g_maskedT[cls * N_OBJn + s_id[tid]] = s_keep[tid] ? s_sc[tid] : 0.0f;
}

// ---------------------------------------------------------------------------
// Kernel 3: argmax, one WARP per object (first-max tie: smaller class wins)
// ---------------------------------------------------------------------------
__global__ void argmax_kernel(float* __restrict__ out)
{
    int wid  = threadIdx.x >> 5;
    int lane = threadIdx.x & 31;
    int obj  = blockIdx.x * 8 + wid;
    if (obj >= N_OBJn) return;

    float bv = -1.0f;
    int   bc = 1000;
#pragma unroll
    for (int s = 0; s < 5; s++) {
        int c = 1 + lane + 32 * s;
        if (c < C_OBJn) {
            float v = g_maskedT[c * N_OBJn + obj];
            if (v > bv || (v == bv && c < bc)) { bv = v; bc = c; }
        }
    }
#pragma unroll
    for (int o = 16; o; o >>= 1) {
        float ov = __shfl_xor_sync(0xffffffffu, bv, o);
        int   oc = __shfl_xor_sync(0xffffffffu, bc, o);
        if (ov > bv || (ov == bv && oc < bc)) { bv = ov; bc = oc; }
    }
    if (lane == 0) out[OUT_PREDS + obj] = (float)bc;
}

// ---------------------------------------------------------------------------
// Kernel 4a: W[51,4096] fp32 -> fp16, padded to 64 rows
// ---------------------------------------------------------------------------
__global__ void wsplit_kernel(const float* __restrict__ W)
{
    int i = blockIdx.x * blockDim.x + threadIdx.x;
    if (i >= 64 * D_DIM) return;
    int n = i >> 12;
    float x = (n < C_RELn) ? W[i] : 0.0f;
    g_Whf[i] = __float2half_rn(x);
}

// ---------------------------------------------------------------------------
// Kernel 4b: fp16 2-product split GEMM via mma.sync
// C = A_hi @ W^T + A_lo @ W^T + b   (A = A_hi + A_lo exact to ~2^-22,
// W fp16-rounded: rel err ~2^-12 over K=4096 dots)
// Tile 64x64, K-chunk 64, grid 256 (2 CTAs/SM). Separate accH/accL chains.
// ---------------------------------------------------------------------------
#define OFF_AHI 0
#define OFF_ALO 8192
#define OFF_WHF 16384
#define BUFSZ   24576
#define SM_TOTAL (2 * BUFSZ)

__device__ __forceinline__ uint32_t pkh2(__half a, __half b) {
    __half2 t = __halves2half2(a, b);
    return *(uint32_t*)&t;
}

__global__ __launch_bounds__(256, 2) void gemm_tc_kernel(const float* __restrict__ A,
                                                         const float* __restrict__ bias,
                                                         float* __restrict__ out)
{
    extern __shared__ char smem[];
    const uint32_t sb = smem_u32(smem);
    const int tid  = threadIdx.x;
    const int lane = tid & 31;
    const int wid  = tid >> 5;
    const int warp_m = wid & 3;   // 16-row block
    const int warp_n = wid >> 2;  // 32-col block
    const int rowBase = blockIdx.x * 64;

    // A loader: row ar+16p (p<4), fp32 quad aq
    const int ar = tid >> 4;
    const int aq = tid & 15;
    const float* aPtr = A + (size_t)(rowBase + ar) * D_DIM + aq * 4;

    float4 ra[4];
    uint4  rw[2];

    auto ldg = [&](int k0) {
#pragma unroll
        for (int p = 0; p < 4; p++)
            ra[p] = *(const float4*)(aPtr + (size_t)16 * p * D_DIM + k0);
#pragma unroll
        for (int u = 0; u < 2; u++) {
            int idx = tid * 2 + u;           // 0..511: n = idx>>3, q = idx&7
            int n = idx >> 3, q = idx & 7;
            rw[u] = *(const uint4*)&g_Whf[(size_t)n * D_DIM + k0 + q * 8];
        }
    };

    auto sts = [&](int buf) {
        char* bp = smem + buf * BUFSZ;
#pragma unroll
        for (int p = 0; p < 4; p++) {
            int r = ar + 16 * p;
            uint32_t off = SW128((uint32_t)(r * 128 + aq * 8));
            float v0 = ra[p].x, v1 = ra[p].y, v2 = ra[p].z, v3 = ra[p].w;
            __half h0 = __float2half_rn(v0), h1 = __float2half_rn(v1);
            __half h2 = __float2half_rn(v2), h3 = __float2half_rn(v3);
            __half l0 = __float2half_rn(v0 - __half2float(h0));
            __half l1 = __float2half_rn(v1 - __half2float(h1));
            __half l2 = __float2half_rn(v2 - __half2float(h2));
            __half l3 = __float2half_rn(v3 - __half2float(h3));
            *(uint2*)(bp + OFF_AHI + off) = make_uint2(pkh2(h0, h1), pkh2(h2, h3));
            *(uint2*)(bp + OFF_ALO + off) = make_uint2(pkh2(l0, l1), pkh2(l2, l3));
        }
#pragma unroll
        for (int u = 0; u < 2; u++) {
            int idx = tid * 2 + u;
            int n = idx >> 3, q = idx & 7;
            uint32_t off = SW128((uint32_t)(n * 128 + q * 16));
            *(uint4*)(bp + OFF_WHF + off) = rw[u];
        }
    };

    float accH[4][4], accL[4][4];
#pragma unroll
    for (int nt = 0; nt < 4; nt++)
#pragma unroll
        for (int e = 0; e < 4; e++) { accH[nt][e] = 0.f; accL[nt][e] = 0.f; }

    // ldmatrix per-thread intra-tile byte offsets (pre-swizzle)
    const uint32_t aRow = (uint32_t)(warp_m * 16 + (lane & 15)) * 128 + (uint32_t)(lane >> 4) * 16;
    const uint32_t bRow = (uint32_t)(warp_n * 32 + ((lane >> 4) & 1) * 8 + (lane & 7)) * 128 +
                          (uint32_t)((lane >> 3) & 1) * 16;

    ldg(0);
    sts(0);
    __syncthreads();

#pragma unroll 1
    for (int i = 0; i < 64; i++) {
        if (i < 63) ldg((i + 1) * 64);

        const uint32_t bb = sb + (uint32_t)(i & 1) * BUFSZ;
#pragma unroll
        for (int kk = 0; kk < 4; kk++) {
            uint32_t aH[4], aL[4], bW[2][4];
            {
                uint32_t o = SW128(aRow + (uint32_t)kk * 32);
                ldmx4(aH, bb + OFF_AHI + o);
                ldmx4(aL, bb + OFF_ALO + o);
            }
#pragma unroll
            for (int pr = 0; pr < 2; pr++) {
                uint32_t o = SW128(bRow + (uint32_t)pr * 2048 + (uint32_t)kk * 32);
                ldmx4(bW[pr], bb + OFF_WHF + o);
            }
#pragma unroll
            for (int nt = 0; nt < 4; nt++) {
                const uint32_t* bw = &bW[nt >> 1][(nt & 1) * 2];
                mma_f16(accH[nt], aH, bw);
                mma_f16(accL[nt], aL, bw);
            }
        }

        if (i < 63) {
            sts((i + 1) & 1);
            __syncthreads();
        }
    }

    // Epilogue: C = accH + accL + bias
    const int g  = lane >> 2;
    const int tg = lane & 3;
    int row0 = rowBase + warp_m * 16 + g;
#pragma unroll
    for (int nt = 0; nt < 4; nt++) {
        int col = warp_n * 32 + nt * 8 + tg * 2;
        if (col < C_RELn) {
            float b0 = bias[col];
            out[OUT_REL + (size_t)row0 * C_RELn + col]       = accH[nt][0] + accL[nt][0] + b0;
            out[OUT_REL + (size_t)(row0 + 8) * C_RELn + col] = accH[nt][2] + accL[nt][2] + b0;
        }
        if (col + 1 < C_RELn) {
            float b1 = bias[col + 1];
            out[OUT_REL + (size_t)row0 * C_RELn + col + 1]       = accH[nt][1] + accL[nt][1] + b1;
            out[OUT_REL + (size_t)(row0 + 8) * C_RELn + col + 1] = accH[nt][3] + accL[nt][3] + b1;
        }
    }
}

// ---------------------------------------------------------------------------
extern "C" void kernel_launch(void* const* d_in, const int* in_sizes, int n_in,
                              void* d_out, int out_size)
{
    (void)in_sizes; (void)n_in; (void)out_size;
    const float* obj_logits = (const float*)d_in[0];
    const float* vr         = (const float*)d_in[1];
    const float* boxes      = (const float*)d_in[2];
    const float* W_vr       = (const float*)d_in[3];
    const float* b_vr       = (const float*)d_in[4];
    float* out = (float*)d_out;

    cudaFuncSetAttribute(gemm_tc_kernel, cudaFuncAttributeMaxDynamicSharedMemorySize, SM_TOTAL);

    // Issue order puts gemm at position 3 (0-based) so the harness ncu capture
    // (which has landed on position 3 in both prior rounds) profiles the GEMM.
    cudaEventRecord(g_fork.e1, 0);
    cudaStreamWaitEvent(g_fork.s2, g_fork.e1, 0);

    wsplit_kernel<<<512, 512>>>(W_vr);                          // pos 0 (main)
    softmax_copy_kernel<<<64, 256, 0, g_fork.s2>>>(obj_logits, out); // pos 1 (s2)
    nms_kernel<<<150, 512, 0, g_fork.s2>>>(boxes);              // pos 2 (s2)
    gemm_tc_kernel<<<N_RELn / 64, 256, SM_TOTAL>>>(vr, b_vr, out);   // pos 3 (main)
    argmax_kernel<<<64, 256, 0, g_fork.s2>>>(out);              // pos 4 (s2)
    cudaEventRecord(g_fork.e2, g_fork.s2);

    cudaStreamWaitEvent(0, g_fork.e2, 0);
}

// round 6
// speedup vs baseline: 1.6207x; 1.6207x over previous
#include <cuda_runtime.h>
#include <cuda_fp16.h>
#include <cstdint>

#define N_OBJn 512
#define C_OBJn 151
#define N_RELn 16384
#define C_RELn 51
#define D_DIM  4096

#define OUT_PREDS  (N_OBJn * C_OBJn)          /* 77312 */
#define OUT_REL    (OUT_PREDS + N_OBJn)       /* 77824 */

// Scratch (device globals — no allocation allowed)
__device__ float g_probsT[C_OBJn * N_OBJn];   // [class][obj]
__device__ float g_maskedT[C_OBJn * N_OBJn];  // [class][obj], class 0 unused
__device__ __align__(16) __half g_Whf[64 * D_DIM];  // W as fp16, rows 51..63 zero

// ---------------------------------------------------------------------------
// helpers
// ---------------------------------------------------------------------------
__device__ __forceinline__ uint32_t smem_u32(const void* p) {
    uint32_t a;
    asm("{ .reg .u64 t; cvta.to.shared.u64 t, %1; cvt.u32.u64 %0, t; }" : "=r"(a) : "l"(p));
    return a;
}
#define SW128(o) ((o) ^ (((o) >> 3) & 0x70))

__device__ __forceinline__ void ldmx4(uint32_t* r, uint32_t addr) {
    asm volatile("ldmatrix.sync.aligned.m8n8.x4.shared.b16 {%0,%1,%2,%3}, [%4];"
                 : "=r"(r[0]), "=r"(r[1]), "=r"(r[2]), "=r"(r[3]) : "r"(addr));
}
__device__ __forceinline__ void mma_f16(float* d, const uint32_t* a, const uint32_t* b) {
    asm volatile(
        "mma.sync.aligned.m16n8k16.row.col.f32.f16.f16.f32 "
        "{%0,%1,%2,%3},{%4,%5,%6,%7},{%8,%9},{%0,%1,%2,%3};"
        : "+f"(d[0]), "+f"(d[1]), "+f"(d[2]), "+f"(d[3])
        : "r"(a[0]), "r"(a[1]), "r"(a[2]), "r"(a[3]), "r"(b[0]), "r"(b[1]));
}

// ---------------------------------------------------------------------------
// Kernel 1: row softmax (one warp per row) + copy logits to out[0:77312)
// ---------------------------------------------------------------------------
__global__ void softmax_copy_kernel(const float* __restrict__ logits,
                                    float* __restrict__ out)
{
    int warp = threadIdx.x >> 5;
    int lane = threadIdx.x & 31;
    int row  = blockIdx.x * 8 + warp;
    if (row >= N_OBJn) return;

    float v[5];
    float mx = -1e30f;
#pragma unroll
    for (int s = 0; s < 5; s++) {
        int c = lane + 32 * s;
        v[s] = (c < C_OBJn) ? logits[row * C_OBJn + c] : -1e30f;
        mx = fmaxf(mx, v[s]);
    }
#pragma unroll
    for (int o = 16; o; o >>= 1) mx = fmaxf(mx, __shfl_xor_sync(0xffffffffu, mx, o));

    float e[5];
    float sum = 0.f;
#pragma unroll
    for (int s = 0; s < 5; s++) {
        int c = lane + 32 * s;
        e[s] = (c < C_OBJn) ? expf(v[s] - mx) : 0.f;
        sum += e[s];
    }
#pragma unroll
    for (int o = 16; o; o >>= 1) sum += __shfl_xor_sync(0xffffffffu, sum, o);

#pragma unroll
    for (int s = 0; s < 5; s++) {
        int c = lane + 32 * s;
        if (c < C_OBJn) {
            g_probsT[c * N_OBJn + row] = __fdiv_rn(e[s], sum);
            out[row * C_OBJn + c] = v[s];   // obj_dists2 passthrough
        }
    }
}

// ---------------------------------------------------------------------------
// Kernel 2: per-class NMS (bit-exact IoU predicate vs JAX)
// ---------------------------------------------------------------------------
__global__ __launch_bounds__(512) void nms_kernel(const float* __restrict__ boxes)
{
    __shared__ float s_sc[512];
    __shared__ int   s_id[512];
    __shared__ float s_x1[512], s_y1[512], s_x2[512], s_y2[512], s_ar[512];
    __shared__ unsigned s_mask[512 * 16];
    __shared__ unsigned char s_keep[512];

    const int tid = threadIdx.x;
    const int cls = blockIdx.x + 1;

    s_sc[tid] = g_probsT[cls * N_OBJn + tid];
    s_id[tid] = tid;
    __syncthreads();

    for (int k = 2; k <= 512; k <<= 1) {
        for (int j = k >> 1; j > 0; j >>= 1) {
            int ixj = tid ^ j;
            if (ixj > tid) {
                float si = s_sc[tid], sj = s_sc[ixj];
                int   ii = s_id[tid], ij = s_id[ixj];
                bool pre_ji = (sj > si) || (sj == si && ij < ii);
                bool dir = ((tid & k) == 0);
                if (dir ? pre_ji : !pre_ji) {
                    s_sc[tid] = sj; s_sc[ixj] = si;
                    s_id[tid] = ij; s_id[ixj] = ii;
                }
            }
            __syncthreads();
        }
    }

    {
        int o = s_id[tid];
        float4 bx = *(const float4*)&boxes[(o * C_OBJn + cls) * 4];
        s_x1[tid] = bx.x; s_y1[tid] = bx.y; s_x2[tid] = bx.z; s_y2[tid] = bx.w;
        s_ar[tid] = __fmul_rn(bx.z - bx.x + 1.0f, bx.w - bx.y + 1.0f);
    }
    __syncthreads();

    {
        int w = tid >> 5, lane = tid & 31;
        for (int ii = 0; ii < 32; ii++) {
            int i = (w << 5) | ii;
            float xi1 = s_x1[i], yi1 = s_y1[i], xi2 = s_x2[i], yi2 = s_y2[i];
            float ai = s_ar[i];
#pragma unroll 4
            for (int cc = 0; cc < 16; cc++) {
                int jx = (cc << 5) | lane;
                float xx1 = fmaxf(xi1, s_x1[jx]);
                float yy1 = fmaxf(yi1, s_y1[jx]);
                float xx2 = fminf(xi2, s_x2[jx]);
                float yy2 = fminf(yi2, s_y2[jx]);
                float wd = fmaxf(xx2 - xx1 + 1.0f, 0.0f);
                float ht = fmaxf(yy2 - yy1 + 1.0f, 0.0f);
                float inter = __fmul_rn(wd, ht);
                float den = ai + s_ar[jx] - inter;
                unsigned m = __ballot_sync(0xffffffffu, __fdiv_rn(inter, den) > 0.3f);
                if (lane == cc) s_mask[(i << 4) + cc] = m;
            }
        }
    }
    __syncthreads();

    if (tid < 32) {
        int lane = tid;
        unsigned sup = 0;
        for (int i = 0; i < 512; i++) {
            unsigned wi = __shfl_sync(0xffffffffu, sup, i >> 5);
            bool keep = ((wi >> (i & 31)) & 1u) == 0u;
            if (keep && lane < 16) sup |= s_mask[(i << 4) + lane];
            if (lane == 0) s_keep[i] = keep ? 1 : 0;
        }
    }
    __syncthreads();

    g_maskedT[cls * N_OBJn + s_id[tid]] = s_keep[tid] ? s_sc[tid] : 0.0f;
}

// ---------------------------------------------------------------------------
// Kernel 3: argmax, one WARP per object (first-max tie: smaller class wins)
// ---------------------------------------------------------------------------
__global__ void argmax_kernel(float* __restrict__ out)
{
    int wid  = threadIdx.x >> 5;
    int lane = threadIdx.x & 31;
    int obj  = blockIdx.x * 8 + wid;
    if (obj >= N_OBJn) return;

    float bv = -1.0f;
    int   bc = 1000;
#pragma unroll
    for (int s = 0; s < 5; s++) {
        int c = 1 + lane + 32 * s;
        if (c < C_OBJn) {
            float v = g_maskedT[c * N_OBJn + obj];
            if (v > bv || (v == bv && c < bc)) { bv = v; bc = c; }
        }
    }
#pragma unroll
    for (int o = 16; o; o >>= 1) {
        float ov = __shfl_xor_sync(0xffffffffu, bv, o);
        int   oc = __shfl_xor_sync(0xffffffffu, bc, o);
        if (ov > bv || (ov == bv && oc < bc)) { bv = ov; bc = oc; }
    }
    if (lane == 0) out[OUT_PREDS + obj] = (float)bc;
}

// ---------------------------------------------------------------------------
// Kernel 4a: W[51,4096] fp32 -> fp16, padded to 64 rows
// ---------------------------------------------------------------------------
__global__ void wsplit_kernel(const float* __restrict__ W)
{
    int i = blockIdx.x * blockDim.x + threadIdx.x;
    if (i >= 64 * D_DIM) return;
    int n = i >> 12;
    float x = (n < C_RELn) ? W[i] : 0.0f;
    g_Whf[i] = __float2half_rn(x);
}

// ---------------------------------------------------------------------------
// Kernel 4b: fp16 2-product split GEMM via mma.sync (UNCHANGED from round 5:
// 74.1us isolated; kept byte-identical to isolate the fork variable)
// ---------------------------------------------------------------------------
#define OFF_AHI 0
#define OFF_ALO 8192
#define OFF_WHF 16384
#define BUFSZ   24576
#define SM_TOTAL (2 * BUFSZ)

__device__ __forceinline__ uint32_t pkh2(__half a, __half b) {
    __half2 t = __halves2half2(a, b);
    return *(uint32_t*)&t;
}

__global__ __launch_bounds__(256, 2) void gemm_tc_kernel(const float* __restrict__ A,
                                                         const float* __restrict__ bias,
                                                         float* __restrict__ out)
{
    extern __shared__ char smem[];
    const uint32_t sb = smem_u32(smem);
    const int tid  = threadIdx.x;
    const int lane = tid & 31;
    const int wid  = tid >> 5;
    const int warp_m = wid & 3;   // 16-row block
    const int warp_n = wid >> 2;  // 32-col block
    const int rowBase = blockIdx.x * 64;

    const int ar = tid >> 4;
    const int aq = tid & 15;
    const float* aPtr = A + (size_t)(rowBase + ar) * D_DIM + aq * 4;

    float4 ra[4];
    uint4  rw[2];

    auto ldg = [&](int k0) {
#pragma unroll
        for (int p = 0; p < 4; p++)
            ra[p] = *(const float4*)(aPtr + (size_t)16 * p * D_DIM + k0);
#pragma unroll
        for (int u = 0; u < 2; u++) {
            int idx = tid * 2 + u;
            int n = idx >> 3, q = idx & 7;
            rw[u] = *(const uint4*)&g_Whf[(size_t)n * D_DIM + k0 + q * 8];
        }
    };

    auto sts = [&](int buf) {
        char* bp = smem + buf * BUFSZ;
#pragma unroll
        for (int p = 0; p < 4; p++) {
            int r = ar + 16 * p;
            uint32_t off = SW128((uint32_t)(r * 128 + aq * 8));
            float v0 = ra[p].x, v1 = ra[p].y, v2 = ra[p].z, v3 = ra[p].w;
            __half h0 = __float2half_rn(v0), h1 = __float2half_rn(v1);
            __half h2 = __float2half_rn(v2), h3 = __float2half_rn(v3);
            __half l0 = __float2half_rn(v0 - __half2float(h0));
            __half l1 = __float2half_rn(v1 - __half2float(h1));
            __half l2 = __float2half_rn(v2 - __half2float(h2));
            __half l3 = __float2half_rn(v3 - __half2float(h3));
            *(uint2*)(bp + OFF_AHI + off) = make_uint2(pkh2(h0, h1), pkh2(h2, h3));
            *(uint2*)(bp + OFF_ALO + off) = make_uint2(pkh2(l0, l1), pkh2(l2, l3));
        }
#pragma unroll
        for (int u = 0; u < 2; u++) {
            int idx = tid * 2 + u;
            int n = idx >> 3, q = idx & 7;
            uint32_t off = SW128((uint32_t)(n * 128 + q * 16));
            *(uint4*)(bp + OFF_WHF + off) = rw[u];
        }
    };

    float accH[4][4], accL[4][4];
#pragma unroll
    for (int nt = 0; nt < 4; nt++)
#pragma unroll
        for (int e = 0; e < 4; e++) { accH[nt][e] = 0.f; accL[nt][e] = 0.f; }

    const uint32_t aRow = (uint32_t)(warp_m * 16 + (lane & 15)) * 128 + (uint32_t)(lane >> 4) * 16;
    const uint32_t bRow = (uint32_t)(warp_n * 32 + ((lane >> 4) & 1) * 8 + (lane & 7)) * 128 +
                          (uint32_t)((lane >> 3) & 1) * 16;

    ldg(0);
    sts(0);
    __syncthreads();

#pragma unroll 1
    for (int i = 0; i < 64; i++) {
        if (i < 63) ldg((i + 1) * 64);

        const uint32_t bb = sb + (uint32_t)(i & 1) * BUFSZ;
#pragma unroll
        for (int kk = 0; kk < 4; kk++) {
            uint32_t aH[4], aL[4], bW[2][4];
            {
                uint32_t o = SW128(aRow + (uint32_t)kk * 32);
                ldmx4(aH, bb + OFF_AHI + o);
                ldmx4(aL, bb + OFF_ALO + o);
            }
#pragma unroll
            for (int pr = 0; pr < 2; pr++) {
                uint32_t o = SW128(bRow + (uint32_t)pr * 2048 + (uint32_t)kk * 32);
                ldmx4(bW[pr], bb + OFF_WHF + o);
            }
#pragma unroll
            for (int nt = 0; nt < 4; nt++) {
                const uint32_t* bw = &bW[nt >> 1][(nt & 1) * 2];
                mma_f16(accH[nt], aH, bw);
                mma_f16(accL[nt], aL, bw);
            }
        }

        if (i < 63) {
            sts((i + 1) & 1);
            __syncthreads();
        }
    }

    const int g  = lane >> 2;
    const int tg = lane & 3;
    int row0 = rowBase + warp_m * 16 + g;
#pragma unroll
    for (int nt = 0; nt < 4; nt++) {
        int col = warp_n * 32 + nt * 8 + tg * 2;
        if (col < C_RELn) {
            float b0 = bias[col];
            out[OUT_REL + (size_t)row0 * C_RELn + col]       = accH[nt][0] + accL[nt][0] + b0;
            out[OUT_REL + (size_t)(row0 + 8) * C_RELn + col] = accH[nt][2] + accL[nt][2] + b0;
        }
        if (col + 1 < C_RELn) {
            float b1 = bias[col + 1];
            out[OUT_REL + (size_t)row0 * C_RELn + col + 1]       = accH[nt][1] + accL[nt][1] + b1;
            out[OUT_REL + (size_t)(row0 + 8) * C_RELn + col + 1] = accH[nt][3] + accL[nt][3] + b1;
        }
    }
}

// ---------------------------------------------------------------------------
// Serial, single-stream pipeline (fork removed — controlled experiment:
// isolates the round-5 regression source). GEMM stays at issue pos 3 for ncu.
// ---------------------------------------------------------------------------
extern "C" void kernel_launch(void* const* d_in, const int* in_sizes, int n_in,
                              void* d_out, int out_size)
{
    (void)in_sizes; (void)n_in; (void)out_size;
    const float* obj_logits = (const float*)d_in[0];
    const float* vr         = (const float*)d_in[1];
    const float* boxes      = (const float*)d_in[2];
    const float* W_vr       = (const float*)d_in[3];
    const float* b_vr       = (const float*)d_in[4];
    float* out = (float*)d_out;

    cudaFuncSetAttribute(gemm_tc_kernel, cudaFuncAttributeMaxDynamicSharedMemorySize, SM_TOTAL);

    wsplit_kernel<<<512, 512>>>(W_vr);                     // pos 0
    softmax_copy_kernel<<<64, 256>>>(obj_logits, out);     // pos 1
    nms_kernel<<<150, 512>>>(boxes);                       // pos 2
    gemm_tc_kernel<<<N_RELn / 64, 256, SM_TOTAL>>>(vr, b_vr, out);  // pos 3
    argmax_kernel<<<64, 256>>>(out);                       // pos 4
}

// round 7
// speedup vs baseline: 1.9923x; 1.2293x over previous
#include <cuda_runtime.h>
#include <cuda_fp16.h>
#include <cstdint>

#define N_OBJn 512
#define C_OBJn 151
#define N_RELn 16384
#define C_RELn 51
#define D_DIM  4096

#define OUT_PREDS  (N_OBJn * C_OBJn)          /* 77312 */
#define OUT_REL    (OUT_PREDS + N_OBJn)       /* 77824 */

// Scratch (device globals — no allocation allowed)
__device__ float g_probsT[C_OBJn * N_OBJn];   // [class][obj]
__device__ float g_maskedT[C_OBJn * N_OBJn];  // [class][obj], class 0 unused
__device__ __align__(16) __half g_Whf[64 * D_DIM];  // W as fp16, rows 51..63 zero

// ---------------------------------------------------------------------------
// helpers
// ---------------------------------------------------------------------------
__device__ __forceinline__ uint32_t smem_u32(const void* p) {
    uint32_t a;
    asm("{ .reg .u64 t; cvta.to.shared.u64 t, %1; cvt.u32.u64 %0, t; }" : "=r"(a) : "l"(p));
    return a;
}
#define SW128(o) ((o) ^ (((o) >> 3) & 0x70))

__device__ __forceinline__ void ldmx4(uint32_t* r, uint32_t addr) {
    asm volatile("ldmatrix.sync.aligned.m8n8.x4.shared.b16 {%0,%1,%2,%3}, [%4];"
                 : "=r"(r[0]), "=r"(r[1]), "=r"(r[2]), "=r"(r[3]) : "r"(addr));
}
__device__ __forceinline__ void mma_f16(float* d, const uint32_t* a, const uint32_t* b) {
    asm volatile(
        "mma.sync.aligned.m16n8k16.row.col.f32.f16.f16.f32 "
        "{%0,%1,%2,%3},{%4,%5,%6,%7},{%8,%9},{%0,%1,%2,%3};"
        : "+f"(d[0]), "+f"(d[1]), "+f"(d[2]), "+f"(d[3])
        : "r"(a[0]), "r"(a[1]), "r"(a[2]), "r"(a[3]), "r"(b[0]), "r"(b[1]));
}

// ---------------------------------------------------------------------------
// Kernel 1: row softmax (one warp per row) + copy logits to out[0:77312)
// ---------------------------------------------------------------------------
__global__ void softmax_copy_kernel(const float* __restrict__ logits,
                                    float* __restrict__ out)
{
    int warp = threadIdx.x >> 5;
    int lane = threadIdx.x & 31;
    int row  = blockIdx.x * 8 + warp;
    if (row >= N_OBJn) return;

    float v[5];
    float mx = -1e30f;
#pragma unroll
    for (int s = 0; s < 5; s++) {
        int c = lane + 32 * s;
        v[s] = (c < C_OBJn) ? logits[row * C_OBJn + c] : -1e30f;
        mx = fmaxf(mx, v[s]);
    }
#pragma unroll
    for (int o = 16; o; o >>= 1) mx = fmaxf(mx, __shfl_xor_sync(0xffffffffu, mx, o));

    float e[5];
    float sum = 0.f;
#pragma unroll
    for (int s = 0; s < 5; s++) {
        int c = lane + 32 * s;
        e[s] = (c < C_OBJn) ? expf(v[s] - mx) : 0.f;
        sum += e[s];
    }
#pragma unroll
    for (int o = 16; o; o >>= 1) sum += __shfl_xor_sync(0xffffffffu, sum, o);

#pragma unroll
    for (int s = 0; s < 5; s++) {
        int c = lane + 32 * s;
        if (c < C_OBJn) {
            g_probsT[c * N_OBJn + row] = __fdiv_rn(e[s], sum);
            out[row * C_OBJn + c] = v[s];   // obj_dists2 passthrough
        }
    }
}

// ---------------------------------------------------------------------------
// Kernel 2: per-class NMS, optimized.
//  - u64-key bitonic sort (score desc, idx asc == ascending of (~bits, idx))
//  - upper-triangle mask build: strip (block b, word cc>=b) -> warp (cc-b paired
//    via cc=(w-b)&15 for balance). Words cc<b are never written: their bits only
//    cover j < i positions whose keep decisions are emitted before any later OR,
//    so garbage there provably cannot affect output.
//  - greedy scan: per 32-block, serial chain is pure ALU (no shfl/LDS in chain).
// IoU math unchanged: __fdiv_rn / explicit rn add-sub, bit-exact vs JAX.
// ---------------------------------------------------------------------------
__global__ __launch_bounds__(512) void nms_kernel(const float* __restrict__ boxes)
{
    __shared__ unsigned long long s_key[512];
    __shared__ float s_x1[512], s_y1[512], s_x2[512], s_y2[512], s_ar[512];
    __shared__ unsigned s_mask[512 * 16];   // 32 KB
    __shared__ unsigned s_keepw[16];

    const int tid  = threadIdx.x;
    const int lane = tid & 31;
    const int w    = tid >> 5;              // 16 warps
    const int cls  = blockIdx.x + 1;

    {
        unsigned sb = __float_as_uint(g_probsT[cls * N_OBJn + tid]);  // probs >= 0
        s_key[tid] = ((unsigned long long)(~sb) << 32) | (unsigned)tid;
    }
    __syncthreads();

    // Ascending bitonic sort of 512 u64 keys
    for (int k = 2; k <= 512; k <<= 1) {
        for (int j = k >> 1; j > 0; j >>= 1) {
            int ixj = tid ^ j;
            if (ixj > tid) {
                unsigned long long a = s_key[tid], b = s_key[ixj];
                bool up = ((tid & k) == 0);
                if ((a > b) == up) { s_key[tid] = b; s_key[ixj] = a; }
            }
            __syncthreads();
        }
    }

    // Load boxes in sorted order
    {
        int o = (int)(s_key[tid] & 0x1FFu);
        float4 bx = *(const float4*)&boxes[(o * C_OBJn + cls) * 4];
        s_x1[tid] = bx.x; s_y1[tid] = bx.y; s_x2[tid] = bx.z; s_y2[tid] = bx.w;
        s_ar[tid] = __fmul_rn(__fadd_rn(__fsub_rn(bx.z, bx.x), 1.0f),
                              __fadd_rn(__fsub_rn(bx.w, bx.y), 1.0f));
    }
    __syncthreads();

    // Mask build: warp w takes strip (b, cc=(w-b)&15) when cc >= b.
    // j-box hoisted to registers once per strip.
#pragma unroll 1
    for (int b = 0; b < 16; b++) {
        int cc = (w - b) & 15;
        if (cc < b) continue;
        int jx = (cc << 5) | lane;
        float jx1 = s_x1[jx], jy1 = s_y1[jx], jx2 = s_x2[jx], jy2 = s_y2[jx];
        float ja  = s_ar[jx];
#pragma unroll 4
        for (int ii = 0; ii < 32; ii++) {
            int i = (b << 5) | ii;
            float xx1 = fmaxf(s_x1[i], jx1);
            float yy1 = fmaxf(s_y1[i], jy1);
            float xx2 = fminf(s_x2[i], jx2);
            float yy2 = fminf(s_y2[i], jy2);
            float wd = fmaxf(__fadd_rn(__fsub_rn(xx2, xx1), 1.0f), 0.0f);
            float ht = fmaxf(__fadd_rn(__fsub_rn(yy2, yy1), 1.0f), 0.0f);
            float inter = __fmul_rn(wd, ht);
            float den = __fsub_rn(__fadd_rn(s_ar[i], ja), inter);
            unsigned m = __ballot_sync(0xffffffffu, __fdiv_rn(inter, den) > 0.3f);
            if (lane == cc) s_mask[(i << 4) + cc] = m;
        }
    }
    __syncthreads();

    // Greedy scan (warp 0). Lane L owns sup word L (L<16).
    if (w == 0) {
        unsigned sup = 0;
#pragma unroll 1
        for (int B = 0; B < 16; B++) {
            unsigned cur = __shfl_sync(0xffffffffu, sup, B);       // word B so far
            unsigned mv  = s_mask[(((B << 5) | lane) << 4) | B];   // row (B*32+lane), word B
            unsigned kb  = 0;
#pragma unroll
            for (int t = 0; t < 32; t++) {
                unsigned mi   = __shfl_sync(0xffffffffu, mv, t);   // off-chain operand
                unsigned keep = ((cur >> t) & 1u) ^ 1u;
                kb  |= keep << t;
                cur |= keep ? mi : 0u;                             // ALU-only chain
            }
            if (lane == 0) s_keepw[B] = kb;
            // fold kept rows into future sup words (off-chain, predicated)
            if (lane < 16) {
#pragma unroll 1
                for (int t = 0; t < 32; t++) {
                    if ((kb >> t) & 1u)
                        sup |= s_mask[(((B << 5) | t) << 4) | lane];
                }
            }
        }
    }
    __syncthreads();

    {
        unsigned kb = s_keepw[tid >> 5];
        bool keep = (kb >> (tid & 31)) & 1u;
        int o = (int)(s_key[tid] & 0x1FFu);
        float sc = __uint_as_float(~(unsigned)(s_key[tid] >> 32));
        g_maskedT[cls * N_OBJn + o] = keep ? sc : 0.0f;
    }
}

// ---------------------------------------------------------------------------
// Kernel 3: argmax, one WARP per object (first-max tie: smaller class wins)
// ---------------------------------------------------------------------------
__global__ void argmax_kernel(float* __restrict__ out)
{
    int wid  = threadIdx.x >> 5;
    int lane = threadIdx.x & 31;
    int obj  = blockIdx.x * 8 + wid;
    if (obj >= N_OBJn) return;

    float bv = -1.0f;
    int   bc = 1000;
#pragma unroll
    for (int s = 0; s < 5; s++) {
        int c = 1 + lane + 32 * s;
        if (c < C_OBJn) {
            float v = g_maskedT[c * N_OBJn + obj];
            if (v > bv || (v == bv && c < bc)) { bv = v; bc = c; }
        }
    }
#pragma unroll
    for (int o = 16; o; o >>= 1) {
        float ov = __shfl_xor_sync(0xffffffffu, bv, o);
        int   oc = __shfl_xor_sync(0xffffffffu, bc, o);
        if (ov > bv || (ov == bv && oc < bc)) { bv = ov; bc = oc; }
    }
    if (lane == 0) out[OUT_PREDS + obj] = (float)bc;
}

// ---------------------------------------------------------------------------
// Kernel 4a: W[51,4096] fp32 -> fp16, padded to 64 rows
// ---------------------------------------------------------------------------
__global__ void wsplit_kernel(const float* __restrict__ W)
{
    int i = blockIdx.x * blockDim.x + threadIdx.x;
    if (i >= 64 * D_DIM) return;
    int n = i >> 12;
    float x = (n < C_RELn) ? W[i] : 0.0f;
    g_Whf[i] = __float2half_rn(x);
}

// ---------------------------------------------------------------------------
// Kernel 4b: fp16 2-product split GEMM via mma.sync (UNCHANGED: 74us measured)
// ---------------------------------------------------------------------------
#define OFF_AHI 0
#define OFF_ALO 8192
#define OFF_WHF 16384
#define BUFSZ   24576
#define SM_TOTAL (2 * BUFSZ)

__device__ __forceinline__ uint32_t pkh2(__half a, __half b) {
    __half2 t = __halves2half2(a, b);
    return *(uint32_t*)&t;
}

__global__ __launch_bounds__(256, 2) void gemm_tc_kernel(const float* __restrict__ A,
                                                         const float* __restrict__ bias,
                                                         float* __restrict__ out)
{
    extern __shared__ char smem[];
    const uint32_t sb = smem_u32(smem);
    const int tid  = threadIdx.x;
    const int lane = tid & 31;
    const int wid  = tid >> 5;
    const int warp_m = wid & 3;
    const int warp_n = wid >> 2;
    const int rowBase = blockIdx.x * 64;

    const int ar = tid >> 4;
    const int aq = tid & 15;
    const float* aPtr = A + (size_t)(rowBase + ar) * D_DIM + aq * 4;

    float4 ra[4];
    uint4  rw[2];

    auto ldg = [&](int k0) {
#pragma unroll
        for (int p = 0; p < 4; p++)
            ra[p] = *(const float4*)(aPtr + (size_t)16 * p * D_DIM + k0);
#pragma unroll
        for (int u = 0; u < 2; u++) {
            int idx = tid * 2 + u;
            int n = idx >> 3, q = idx & 7;
            rw[u] = *(const uint4*)&g_Whf[(size_t)n * D_DIM + k0 + q * 8];
        }
    };

    auto sts = [&](int buf) {
        char* bp = smem + buf * BUFSZ;
#pragma unroll
        for (int p = 0; p < 4; p++) {
            int r = ar + 16 * p;
            uint32_t off = SW128((uint32_t)(r * 128 + aq * 8));
            float v0 = ra[p].x, v1 = ra[p].y, v2 = ra[p].z, v3 = ra[p].w;
            __half h0 = __float2half_rn(v0), h1 = __float2half_rn(v1);
            __half h2 = __float2half_rn(v2), h3 = __float2half_rn(v3);
            __half l0 = __float2half_rn(v0 - __half2float(h0));
            __half l1 = __float2half_rn(v1 - __half2float(h1));
            __half l2 = __float2half_rn(v2 - __half2float(h2));
            __half l3 = __float2half_rn(v3 - __half2float(h3));
            *(uint2*)(bp + OFF_AHI + off) = make_uint2(pkh2(h0, h1), pkh2(h2, h3));
            *(uint2*)(bp + OFF_ALO + off) = make_uint2(pkh2(l0, l1), pkh2(l2, l3));
        }
#pragma unroll
        for (int u = 0; u < 2; u++) {
            int idx = tid * 2 + u;
            int n = idx >> 3, q = idx & 7;
            uint32_t off = SW128((uint32_t)(n * 128 + q * 16));
            *(uint4*)(bp + OFF_WHF + off) = rw[u];
        }
    };

    float accH[4][4], accL[4][4];
#pragma unroll
    for (int nt = 0; nt < 4; nt++)
#pragma unroll
        for (int e = 0; e < 4; e++) { accH[nt][e] = 0.f; accL[nt][e] = 0.f; }

    const uint32_t aRow = (uint32_t)(warp_m * 16 + (lane & 15)) * 128 + (uint32_t)(lane >> 4) * 16;
    const uint32_t bRow = (uint32_t)(warp_n * 32 + ((lane >> 4) & 1) * 8 + (lane & 7)) * 128 +
                          (uint32_t)((lane >> 3) & 1) * 16;

    ldg(0);
    sts(0);
    __syncthreads();

#pragma unroll 1
    for (int i = 0; i < 64; i++) {
        if (i < 63) ldg((i + 1) * 64);

        const uint32_t bb = sb + (uint32_t)(i & 1) * BUFSZ;
#pragma unroll
        for (int kk = 0; kk < 4; kk++) {
            uint32_t aH[4], aL[4], bW[2][4];
            {
                uint32_t o = SW128(aRow + (uint32_t)kk * 32);
                ldmx4(aH, bb + OFF_AHI + o);
                ldmx4(aL, bb + OFF_ALO + o);
            }
#pragma unroll
            for (int pr = 0; pr < 2; pr++) {
                uint32_t o = SW128(bRow + (uint32_t)pr * 2048 + (uint32_t)kk * 32);
                ldmx4(bW[pr], bb + OFF_WHF + o);
            }
#pragma unroll
            for (int nt = 0; nt < 4; nt++) {
                const uint32_t* bw = &bW[nt >> 1][(nt & 1) * 2];
                mma_f16(accH[nt], aH, bw);
                mma_f16(accL[nt], aL, bw);
            }
        }

        if (i < 63) {
            sts((i + 1) & 1);
            __syncthreads();
        }
    }

    const int g  = lane >> 2;
    const int tg = lane & 3;
    int row0 = rowBase + warp_m * 16 + g;
#pragma unroll
    for (int nt = 0; nt < 4; nt++) {
        int col = warp_n * 32 + nt * 8 + tg * 2;
        if (col < C_RELn) {
            float b0 = bias[col];
            out[OUT_REL + (size_t)row0 * C_RELn + col]       = accH[nt][0] + accL[nt][0] + b0;
            out[OUT_REL + (size_t)(row0 + 8) * C_RELn + col] = accH[nt][2] + accL[nt][2] + b0;
        }
        if (col + 1 < C_RELn) {
            float b1 = bias[col + 1];
            out[OUT_REL + (size_t)row0 * C_RELn + col + 1]       = accH[nt][1] + accL[nt][1] + b1;
            out[OUT_REL + (size_t)(row0 + 8) * C_RELn + col + 1] = accH[nt][3] + accL[nt][3] + b1;
        }
    }
}

// ---------------------------------------------------------------------------
// Serial pipeline; nms at issue position 3 so ncu (which has captured pos 3)
// finally profiles it.
// ---------------------------------------------------------------------------
extern "C" void kernel_launch(void* const* d_in, const int* in_sizes, int n_in,
                              void* d_out, int out_size)
{
    (void)in_sizes; (void)n_in; (void)out_size;
    const float* obj_logits = (const float*)d_in[0];
    const float* vr         = (const float*)d_in[1];
    const float* boxes      = (const float*)d_in[2];
    const float* W_vr       = (const float*)d_in[3];
    const float* b_vr       = (const float*)d_in[4];
    float* out = (float*)d_out;

    cudaFuncSetAttribute(gemm_tc_kernel, cudaFuncAttributeMaxDynamicSharedMemorySize, SM_TOTAL);

    wsplit_kernel<<<512, 512>>>(W_vr);                               // pos 0
    softmax_copy_kernel<<<64, 256>>>(obj_logits, out);               // pos 1
    gemm_tc_kernel<<<N_RELn / 64, 256, SM_TOTAL>>>(vr, b_vr, out);   // pos 2
    nms_kernel<<<150, 512>>>(boxes);                                 // pos 3
    argmax_kernel<<<64, 256>>>(out);                                 // pos 4
}

// round 8
// speedup vs baseline: 2.0985x; 1.0533x over previous
#include <cuda_runtime.h>
#include <cuda_fp16.h>
#include <cstdint>

#define N_OBJn 512
#define C_OBJn 151
#define N_RELn 16384
#define C_RELn 51
#define D_DIM  4096

#define OUT_PREDS  (N_OBJn * C_OBJn)          /* 77312 */
#define OUT_REL    (OUT_PREDS + N_OBJn)       /* 77824 */

// Scratch (device globals — no allocation allowed)
__device__ float g_probsT[C_OBJn * N_OBJn];   // [class][obj]
__device__ float g_maskedT[C_OBJn * N_OBJn];  // [class][obj], class 0 unused
__device__ __align__(16) __half g_Whf[64 * D_DIM];  // W as fp16, rows 51..63 zero

// ---------------------------------------------------------------------------
// helpers
// ---------------------------------------------------------------------------
__device__ __forceinline__ uint32_t smem_u32(const void* p) {
    uint32_t a;
    asm("{ .reg .u64 t; cvta.to.shared.u64 t, %1; cvt.u32.u64 %0, t; }" : "=r"(a) : "l"(p));
    return a;
}
#define SW128(o) ((o) ^ (((o) >> 3) & 0x70))

__device__ __forceinline__ void ldmx4(uint32_t* r, uint32_t addr) {
    asm volatile("ldmatrix.sync.aligned.m8n8.x4.shared.b16 {%0,%1,%2,%3}, [%4];"
                 : "=r"(r[0]), "=r"(r[1]), "=r"(r[2]), "=r"(r[3]) : "r"(addr));
}
__device__ __forceinline__ void mma_f16(float* d, const uint32_t* a, const uint32_t* b) {
    asm volatile(
        "mma.sync.aligned.m16n8k16.row.col.f32.f16.f16.f32 "
        "{%0,%1,%2,%3},{%4,%5,%6,%7},{%8,%9},{%0,%1,%2,%3};"
        : "+f"(d[0]), "+f"(d[1]), "+f"(d[2]), "+f"(d[3])
        : "r"(a[0]), "r"(a[1]), "r"(a[2]), "r"(a[3]), "r"(b[0]), "r"(b[1]));
}

// ---------------------------------------------------------------------------
// Kernel 1: row softmax (one warp per row) + copy logits to out[0:77312)
// ---------------------------------------------------------------------------
__global__ void softmax_copy_kernel(const float* __restrict__ logits,
                                    float* __restrict__ out)
{
    int warp = threadIdx.x >> 5;
    int lane = threadIdx.x & 31;
    int row  = blockIdx.x * 8 + warp;
    if (row >= N_OBJn) return;

    float v[5];
    float mx = -1e30f;
#pragma unroll
    for (int s = 0; s < 5; s++) {
        int c = lane + 32 * s;
        v[s] = (c < C_OBJn) ? logits[row * C_OBJn + c] : -1e30f;
        mx = fmaxf(mx, v[s]);
    }
#pragma unroll
    for (int o = 16; o; o >>= 1) mx = fmaxf(mx, __shfl_xor_sync(0xffffffffu, mx, o));

    float e[5];
    float sum = 0.f;
#pragma unroll
    for (int s = 0; s < 5; s++) {
        int c = lane + 32 * s;
        e[s] = (c < C_OBJn) ? expf(v[s] - mx) : 0.f;
        sum += e[s];
    }
#pragma unroll
    for (int o = 16; o; o >>= 1) sum += __shfl_xor_sync(0xffffffffu, sum, o);

#pragma unroll
    for (int s = 0; s < 5; s++) {
        int c = lane + 32 * s;
        if (c < C_OBJn) {
            g_probsT[c * N_OBJn + row] = __fdiv_rn(e[s], sum);
            out[row * C_OBJn + c] = v[s];   // obj_dists2 passthrough
        }
    }
}

// ---------------------------------------------------------------------------
// Kernel 2: per-class NMS — LAZY block-greedy rewrite.
//  - u64-key bitonic sort (unchanged, proven)
//  - per 32-block: (1) 32x32 diag IoU mask (2 ballot-rows/warp),
//    (2) redundant 32-step ALU keep-chain in every warp,
//    (3) kept rows suppress FUTURE columns only: each thread owns its column
//        box in registers, accumulates one suppressed bit, 1 ballot/block.
//  Output-identical to eager version: bits for decided columns never re-read;
//  in-block suppression flows only through the diag chain.
//  IoU predicate bit-exact vs JAX (__fdiv_rn, rn add/sub, same op order).
// ---------------------------------------------------------------------------
__global__ __launch_bounds__(512) void nms_kernel(const float* __restrict__ boxes)
{
    __shared__ unsigned long long s_key[512];
    __shared__ float s_x1[512], s_y1[512], s_x2[512], s_y2[512], s_ar[512];
    __shared__ unsigned s_diag[32];
    __shared__ unsigned s_sup[16];
    __shared__ unsigned s_keep[16];

    const int tid  = threadIdx.x;
    const int lane = tid & 31;
    const int w    = tid >> 5;              // 16 warps
    const int cls  = blockIdx.x + 1;

    {
        unsigned sb = __float_as_uint(g_probsT[cls * N_OBJn + tid]);  // probs >= 0
        s_key[tid] = ((unsigned long long)(~sb) << 32) | (unsigned)tid;
    }
    if (tid < 16) s_sup[tid] = 0u;
    __syncthreads();

    // Ascending bitonic sort of 512 u64 keys  == score desc, idx asc
    for (int k = 2; k <= 512; k <<= 1) {
        for (int j = k >> 1; j > 0; j >>= 1) {
            int ixj = tid ^ j;
            if (ixj > tid) {
                unsigned long long a = s_key[tid], b = s_key[ixj];
                bool up = ((tid & k) == 0);
                if ((a > b) == up) { s_key[tid] = b; s_key[ixj] = a; }
            }
            __syncthreads();
        }
    }

    // Load boxes in sorted order; keep own column box in registers
    float cx1, cy1, cx2, cy2, ca;
    {
        int o = (int)(s_key[tid] & 0x1FFu);
        float4 bx = *(const float4*)&boxes[(o * C_OBJn + cls) * 4];
        cx1 = bx.x; cy1 = bx.y; cx2 = bx.z; cy2 = bx.w;
        ca = __fmul_rn(__fadd_rn(__fsub_rn(bx.z, bx.x), 1.0f),
                       __fadd_rn(__fsub_rn(bx.w, bx.y), 1.0f));
        s_x1[tid] = cx1; s_y1[tid] = cy1; s_x2[tid] = cx2; s_y2[tid] = cy2;
        s_ar[tid] = ca;
    }
    __syncthreads();

    unsigned supbit = 0;   // this thread's column suppressed-so-far flag

#pragma unroll 1
    for (int B = 0; B < 16; B++) {
        // (1) diag block: warp w computes rows 2w, 2w+1 of block B
#pragma unroll
        for (int rr = 0; rr < 2; rr++) {
            int r = (B << 5) + (w << 1) + rr;
            float ix1 = s_x1[r], iy1 = s_y1[r], ix2 = s_x2[r], iy2 = s_y2[r];
            float ia  = s_ar[r];
            int c = (B << 5) + lane;
            float xx1 = fmaxf(ix1, s_x1[c]);
            float yy1 = fmaxf(iy1, s_y1[c]);
            float xx2 = fminf(ix2, s_x2[c]);
            float yy2 = fminf(iy2, s_y2[c]);
            float wd = fmaxf(__fadd_rn(__fsub_rn(xx2, xx1), 1.0f), 0.0f);
            float ht = fmaxf(__fadd_rn(__fsub_rn(yy2, yy1), 1.0f), 0.0f);
            float inter = __fmul_rn(wd, ht);
            float den = __fsub_rn(__fadd_rn(ia, s_ar[c]), inter);
            unsigned m = __ballot_sync(0xffffffffu, __fdiv_rn(inter, den) > 0.3f);
            if (lane == 0) s_diag[(w << 1) + rr] = m;
        }
        __syncthreads();

        // (2) keep-chain, redundant per warp (pure ALU, fully unrolled)
        unsigned cur = s_sup[B];
        unsigned kb  = 0;
#pragma unroll
        for (int t = 0; t < 32; t++) {
            unsigned mi   = s_diag[t];
            unsigned keep = ((cur >> t) & 1u) ^ 1u;
            kb  |= keep << t;
            cur |= keep ? mi : 0u;
        }
        if (tid == 0) s_keep[B] = kb;

        // (3) kept rows of block B suppress future columns (w > B only)
        if (w > B) {
            unsigned bits = kb;
            while (bits) {
                int t = __ffs(bits) - 1;
                bits &= bits - 1;
                int i = (B << 5) + t;
                float xx1 = fmaxf(s_x1[i], cx1);
                float yy1 = fmaxf(s_y1[i], cy1);
                float xx2 = fminf(s_x2[i], cx2);
                float yy2 = fminf(s_y2[i], cy2);
                float wd = fmaxf(__fadd_rn(__fsub_rn(xx2, xx1), 1.0f), 0.0f);
                float ht = fmaxf(__fadd_rn(__fsub_rn(yy2, yy1), 1.0f), 0.0f);
                float inter = __fmul_rn(wd, ht);
                float den = __fsub_rn(__fadd_rn(s_ar[i], ca), inter);
                supbit |= (__fdiv_rn(inter, den) > 0.3f) ? 1u : 0u;
            }
            unsigned m = __ballot_sync(0xffffffffu, supbit);
            if (lane == 0) s_sup[w] = m;   // cumulative overwrite, own word only
        }
        __syncthreads();
    }

    {
        unsigned kb = s_keep[w];
        bool keep = (kb >> lane) & 1u;
        int o = (int)(s_key[tid] & 0x1FFu);
        float sc = __uint_as_float(~(unsigned)(s_key[tid] >> 32));
        g_maskedT[cls * N_OBJn + o] = keep ? sc : 0.0f;
    }
}

// ---------------------------------------------------------------------------
// Kernel 3: argmax, one WARP per object (first-max tie: smaller class wins)
// ---------------------------------------------------------------------------
__global__ void argmax_kernel(float* __restrict__ out)
{
    int wid  = threadIdx.x >> 5;
    int lane = threadIdx.x & 31;
    int obj  = blockIdx.x * 8 + wid;
    if (obj >= N_OBJn) return;

    float bv = -1.0f;
    int   bc = 1000;
#pragma unroll
    for (int s = 0; s < 5; s++) {
        int c = 1 + lane + 32 * s;
        if (c < C_OBJn) {
            float v = g_maskedT[c * N_OBJn + obj];
            if (v > bv || (v == bv && c < bc)) { bv = v; bc = c; }
        }
    }
#pragma unroll
    for (int o = 16; o; o >>= 1) {
        float ov = __shfl_xor_sync(0xffffffffu, bv, o);
        int   oc = __shfl_xor_sync(0xffffffffu, bc, o);
        if (ov > bv || (ov == bv && oc < bc)) { bv = ov; bc = oc; }
    }
    if (lane == 0) out[OUT_PREDS + obj] = (float)bc;
}

// ---------------------------------------------------------------------------
// Kernel 4a: W[51,4096] fp32 -> fp16, padded to 64 rows
// ---------------------------------------------------------------------------
__global__ void wsplit_kernel(const float* __restrict__ W)
{
    int i = blockIdx.x * blockDim.x + threadIdx.x;
    if (i >= 64 * D_DIM) return;
    int n = i >> 12;
    float x = (n < C_RELn) ? W[i] : 0.0f;
    g_Whf[i] = __float2half_rn(x);
}

// ---------------------------------------------------------------------------
// Kernel 4b: fp16 2-product split GEMM via mma.sync (UNCHANGED: 74us measured)
// ---------------------------------------------------------------------------
#define OFF_AHI 0
#define OFF_ALO 8192
#define OFF_WHF 16384
#define BUFSZ   24576
#define SM_TOTAL (2 * BUFSZ)

__device__ __forceinline__ uint32_t pkh2(__half a, __half b) {
    __half2 t = __halves2half2(a, b);
    return *(uint32_t*)&t;
}

__global__ __launch_bounds__(256, 2) void gemm_tc_kernel(const float* __restrict__ A,
                                                         const float* __restrict__ bias,
                                                         float* __restrict__ out)
{
    extern __shared__ char smem[];
    const uint32_t sb = smem_u32(smem);
    const int tid  = threadIdx.x;
    const int lane = tid & 31;
    const int wid  = tid >> 5;
    const int warp_m = wid & 3;
    const int warp_n = wid >> 2;
    const int rowBase = blockIdx.x * 64;

    const int ar = tid >> 4;
    const int aq = tid & 15;
    const float* aPtr = A + (size_t)(rowBase + ar) * D_DIM + aq * 4;

    float4 ra[4];
    uint4  rw[2];

    auto ldg = [&](int k0) {
#pragma unroll
        for (int p = 0; p < 4; p++)
            ra[p] = *(const float4*)(aPtr + (size_t)16 * p * D_DIM + k0);
#pragma unroll
        for (int u = 0; u < 2; u++) {
            int idx = tid * 2 + u;
            int n = idx >> 3, q = idx & 7;
            rw[u] = *(const uint4*)&g_Whf[(size_t)n * D_DIM + k0 + q * 8];
        }
    };

    auto sts = [&](int buf) {
        char* bp = smem + buf * BUFSZ;
#pragma unroll
        for (int p = 0; p < 4; p++) {
            int r = ar + 16 * p;
            uint32_t off = SW128((uint32_t)(r * 128 + aq * 8));
            float v0 = ra[p].x, v1 = ra[p].y, v2 = ra[p].z, v3 = ra[p].w;
            __half h0 = __float2half_rn(v0), h1 = __float2half_rn(v1);
            __half h2 = __float2half_rn(v2), h3 = __float2half_rn(v3);
            __half l0 = __float2half_rn(v0 - __half2float(h0));
            __half l1 = __float2half_rn(v1 - __half2float(h1));
            __half l2 = __float2half_rn(v2 - __half2float(h2));
            __half l3 = __float2half_rn(v3 - __half2float(h3));
            *(uint2*)(bp + OFF_AHI + off) = make_uint2(pkh2(h0, h1), pkh2(h2, h3));
            *(uint2*)(bp + OFF_ALO + off) = make_uint2(pkh2(l0, l1), pkh2(l2, l3));
        }
#pragma unroll
        for (int u = 0; u < 2; u++) {
            int idx = tid * 2 + u;
            int n = idx >> 3, q = idx & 7;
            uint32_t off = SW128((uint32_t)(n * 128 + q * 16));
            *(uint4*)(bp + OFF_WHF + off) = rw[u];
        }
    };

    float accH[4][4], accL[4][4];
#pragma unroll
    for (int nt = 0; nt < 4; nt++)
#pragma unroll
        for (int e = 0; e < 4; e++) { accH[nt][e] = 0.f; accL[nt][e] = 0.f; }

    const uint32_t aRow = (uint32_t)(warp_m * 16 + (lane & 15)) * 128 + (uint32_t)(lane >> 4) * 16;
    const uint32_t bRow = (uint32_t)(warp_n * 32 + ((lane >> 4) & 1) * 8 + (lane & 7)) * 128 +
                          (uint32_t)((lane >> 3) & 1) * 16;

    ldg(0);
    sts(0);
    __syncthreads();

#pragma unroll 1
    for (int i = 0; i < 64; i++) {
        if (i < 63) ldg((i + 1) * 64);

        const uint32_t bb = sb + (uint32_t)(i & 1) * BUFSZ;
#pragma unroll
        for (int kk = 0; kk < 4; kk++) {
            uint32_t aH[4], aL[4], bW[2][4];
            {
                uint32_t o = SW128(aRow + (uint32_t)kk * 32);
                ldmx4(aH, bb + OFF_AHI + o);
                ldmx4(aL, bb + OFF_ALO + o);
            }
#pragma unroll
            for (int pr = 0; pr < 2; pr++) {
                uint32_t o = SW128(bRow + (uint32_t)pr * 2048 + (uint32_t)kk * 32);
                ldmx4(bW[pr], bb + OFF_WHF + o);
            }
#pragma unroll
            for (int nt = 0; nt < 4; nt++) {
                const uint32_t* bw = &bW[nt >> 1][(nt & 1) * 2];
                mma_f16(accH[nt], aH, bw);
                mma_f16(accL[nt], aL, bw);
            }
        }

        if (i < 63) {
            sts((i + 1) & 1);
            __syncthreads();
        }
    }

    const int g  = lane >> 2;
    const int tg = lane & 3;
    int row0 = rowBase + warp_m * 16 + g;
#pragma unroll
    for (int nt = 0; nt < 4; nt++) {
        int col = warp_n * 32 + nt * 8 + tg * 2;
        if (col < C_RELn) {
            float b0 = bias[col];
            out[OUT_REL + (size_t)row0 * C_RELn + col]       = accH[nt][0] + accL[nt][0] + b0;
            out[OUT_REL + (size_t)(row0 + 8) * C_RELn + col] = accH[nt][2] + accL[nt][2] + b0;
        }
        if (col + 1 < C_RELn) {
            float b1 = bias[col + 1];
            out[OUT_REL + (size_t)row0 * C_RELn + col + 1]       = accH[nt][1] + accL[nt][1] + b1;
            out[OUT_REL + (size_t)(row0 + 8) * C_RELn + col + 1] = accH[nt][3] + accL[nt][3] + b1;
        }
    }
}

// ---------------------------------------------------------------------------
// Serial pipeline; nms at issue position 3 so ncu profiles the rewrite.
// ---------------------------------------------------------------------------
extern "C" void kernel_launch(void* const* d_in, const int* in_sizes, int n_in,
                              void* d_out, int out_size)
{
    (void)in_sizes; (void)n_in; (void)out_size;
    const float* obj_logits = (const float*)d_in[0];
    const float* vr         = (const float*)d_in[1];
    const float* boxes      = (const float*)d_in[2];
    const float* W_vr       = (const float*)d_in[3];
    const float* b_vr       = (const float*)d_in[4];
    float* out = (float*)d_out;

    cudaFuncSetAttribute(gemm_tc_kernel, cudaFuncAttributeMaxDynamicSharedMemorySize, SM_TOTAL);

    wsplit_kernel<<<512, 512>>>(W_vr);                               // pos 0
    softmax_copy_kernel<<<64, 256>>>(obj_logits, out);               // pos 1
    gemm_tc_kernel<<<N_RELn / 64, 256, SM_TOTAL>>>(vr, b_vr, out);   // pos 2
    nms_kernel<<<150, 512>>>(boxes);                                 // pos 3
    argmax_kernel<<<64, 256>>>(out);                                 // pos 4
}

// round 9
// speedup vs baseline: 2.7626x; 1.3164x over previous
#include <cuda_runtime.h>
#include <cuda_fp16.h>
#include <cstdint>

#define N_OBJn 512
#define C_OBJn 151
#define N_RELn 16384
#define C_RELn 51
#define D_DIM  4096

#define OUT_PREDS  (N_OBJn * C_OBJn)          /* 77312 */
#define OUT_REL    (OUT_PREDS + N_OBJn)       /* 77824 */

// Scratch (device globals — no allocation allowed)
__device__ float g_probsT[C_OBJn * N_OBJn];   // [class][obj]
__device__ float g_maskedT[C_OBJn * N_OBJn];  // [class][obj], class 0 unused
__device__ __align__(16) __half g_Whf[64 * D_DIM];  // W as fp16, rows 51..63 zero

// ---------------------------------------------------------------------------
// helpers
// ---------------------------------------------------------------------------
__device__ __forceinline__ uint32_t smem_u32(const void* p) {
    uint32_t a;
    asm("{ .reg .u64 t; cvta.to.shared.u64 t, %1; cvt.u32.u64 %0, t; }" : "=r"(a) : "l"(p));
    return a;
}
#define SW128(o) ((o) ^ (((o) >> 3) & 0x70))

__device__ __forceinline__ void ldmx4(uint32_t* r, uint32_t addr) {
    asm volatile("ldmatrix.sync.aligned.m8n8.x4.shared.b16 {%0,%1,%2,%3}, [%4];"
                 : "=r"(r[0]), "=r"(r[1]), "=r"(r[2]), "=r"(r[3]) : "r"(addr));
}
__device__ __forceinline__ void mma_f16(float* d, const uint32_t* a, const uint32_t* b) {
    asm volatile(
        "mma.sync.aligned.m16n8k16.row.col.f32.f16.f16.f32 "
        "{%0,%1,%2,%3},{%4,%5,%6,%7},{%8,%9},{%0,%1,%2,%3};"
        : "+f"(d[0]), "+f"(d[1]), "+f"(d[2]), "+f"(d[3])
        : "r"(a[0]), "r"(a[1]), "r"(a[2]), "r"(a[3]), "r"(b[0]), "r"(b[1]));
}

// Exact IoU>0.3 predicate, division-free fast path.
// t = RN(0.3*den). Exact boundary m*den and t both lie within ~6e-8 rel of
// 0.3*den, so |inter-t| >= 4e-7*t  =>  sign(inter-t) == exact predicate.
// Borderline (~1e-6 probability) falls back to the true rounded division.
__device__ __forceinline__ bool iou_gt(float inter, float den) {
    float t    = __fmul_rn(0.3f, den);
    float diff = __fsub_rn(inter, t);
    bool pred  = diff > 0.0f;
    if (fabsf(diff) < __fmul_rn(t, 4e-7f))
        pred = __fdiv_rn(inter, den) > 0.3f;
    return pred;
}

__device__ __forceinline__ float iou_inter(const float4& a, const float4& b) {
    float xx1 = fmaxf(a.x, b.x);
    float yy1 = fmaxf(a.y, b.y);
    float xx2 = fminf(a.z, b.z);
    float yy2 = fminf(a.w, b.w);
    float wd = fmaxf(__fadd_rn(__fsub_rn(xx2, xx1), 1.0f), 0.0f);
    float ht = fmaxf(__fadd_rn(__fsub_rn(yy2, yy1), 1.0f), 0.0f);
    return __fmul_rn(wd, ht);
}

// ---------------------------------------------------------------------------
// Kernel 1: row softmax (one warp per row) + copy logits to out[0:77312)
// ---------------------------------------------------------------------------
__global__ void softmax_copy_kernel(const float* __restrict__ logits,
                                    float* __restrict__ out)
{
    int warp = threadIdx.x >> 5;
    int lane = threadIdx.x & 31;
    int row  = blockIdx.x * 8 + warp;
    if (row >= N_OBJn) return;

    float v[5];
    float mx = -1e30f;
#pragma unroll
    for (int s = 0; s < 5; s++) {
        int c = lane + 32 * s;
        v[s] = (c < C_OBJn) ? logits[row * C_OBJn + c] : -1e30f;
        mx = fmaxf(mx, v[s]);
    }
#pragma unroll
    for (int o = 16; o; o >>= 1) mx = fmaxf(mx, __shfl_xor_sync(0xffffffffu, mx, o));

    float e[5];
    float sum = 0.f;
#pragma unroll
    for (int s = 0; s < 5; s++) {
        int c = lane + 32 * s;
        e[s] = (c < C_OBJn) ? expf(v[s] - mx) : 0.f;
        sum += e[s];
    }
#pragma unroll
    for (int o = 16; o; o >>= 1) sum += __shfl_xor_sync(0xffffffffu, sum, o);

#pragma unroll
    for (int s = 0; s < 5; s++) {
        int c = lane + 32 * s;
        if (c < C_OBJn) {
            g_probsT[c * N_OBJn + row] = __fdiv_rn(e[s], sum);
            out[row * C_OBJn + c] = v[s];   // obj_dists2 passthrough
        }
    }
}

// ---------------------------------------------------------------------------
// Kernel 2: per-class NMS — lazy block-greedy + division-free IoU predicate
// + float4-packed box SMEM.
// ---------------------------------------------------------------------------
__global__ __launch_bounds__(512) void nms_kernel(const float* __restrict__ boxes)
{
    __shared__ unsigned long long s_key[512];
    __shared__ float4 s_box[512];
    __shared__ float  s_ar[512];
    __shared__ unsigned s_diag[32];
    __shared__ unsigned s_sup[16];
    __shared__ unsigned s_keep[16];

    const int tid  = threadIdx.x;
    const int lane = tid & 31;
    const int w    = tid >> 5;              // 16 warps
    const int cls  = blockIdx.x + 1;

    {
        unsigned sb = __float_as_uint(g_probsT[cls * N_OBJn + tid]);  // probs >= 0
        s_key[tid] = ((unsigned long long)(~sb) << 32) | (unsigned)tid;
    }
    if (tid < 16) s_sup[tid] = 0u;
    __syncthreads();

    // Ascending bitonic sort of 512 u64 keys  == score desc, idx asc
    for (int k = 2; k <= 512; k <<= 1) {
        for (int j = k >> 1; j > 0; j >>= 1) {
            int ixj = tid ^ j;
            if (ixj > tid) {
                unsigned long long a = s_key[tid], b = s_key[ixj];
                bool up = ((tid & k) == 0);
                if ((a > b) == up) { s_key[tid] = b; s_key[ixj] = a; }
            }
            __syncthreads();
        }
    }

    // Load boxes in sorted order; own column box stays in registers
    float4 cb;
    float  ca;
    {
        int o = (int)(s_key[tid] & 0x1FFu);
        cb = *(const float4*)&boxes[(o * C_OBJn + cls) * 4];
        ca = __fmul_rn(__fadd_rn(__fsub_rn(cb.z, cb.x), 1.0f),
                       __fadd_rn(__fsub_rn(cb.w, cb.y), 1.0f));
        s_box[tid] = cb;
        s_ar[tid]  = ca;
    }
    __syncthreads();

    unsigned supbit = 0;   // this thread's column suppressed-so-far flag

#pragma unroll 1
    for (int B = 0; B < 16; B++) {
        // (1) diag block: warp w computes rows 2w, 2w+1; col box hoisted per B
        {
            float4 db = s_box[(B << 5) + lane];
            float  da = s_ar[(B << 5) + lane];
#pragma unroll
            for (int rr = 0; rr < 2; rr++) {
                int r = (B << 5) + (w << 1) + rr;
                float4 rb = s_box[r];
                float  ra = s_ar[r];
                float inter = iou_inter(rb, db);
                float den = __fsub_rn(__fadd_rn(ra, da), inter);
                unsigned m = __ballot_sync(0xffffffffu, iou_gt(inter, den));
                if (lane == 0) s_diag[(w << 1) + rr] = m;
            }
        }
        __syncthreads();

        // (2) keep-chain, redundant per warp (pure ALU, fully unrolled)
        unsigned cur = s_sup[B];
        unsigned kb  = 0;
#pragma unroll
        for (int t = 0; t < 32; t++) {
            unsigned mi   = s_diag[t];
            unsigned keep = ((cur >> t) & 1u) ^ 1u;
            kb  |= keep << t;
            cur |= keep ? mi : 0u;
        }
        if (tid == 0) s_keep[B] = kb;

        // (3) kept rows of block B suppress future columns (w > B only)
        if (w > B) {
            unsigned bits = kb;
            while (bits) {
                int t = __ffs(bits) - 1;
                bits &= bits - 1;
                int i = (B << 5) + t;
                float4 ib = s_box[i];         // warp-uniform broadcast LDS.128
                float  ia = s_ar[i];
                float inter = iou_inter(ib, cb);
                float den = __fsub_rn(__fadd_rn(ia, ca), inter);
                supbit |= iou_gt(inter, den) ? 1u : 0u;
            }
            unsigned m = __ballot_sync(0xffffffffu, supbit);
            if (lane == 0) s_sup[w] = m;   // cumulative overwrite, own word only
        }
        __syncthreads();
    }

    {
        unsigned kb = s_keep[w];
        bool keep = (kb >> lane) & 1u;
        int o = (int)(s_key[tid] & 0x1FFu);
        float sc = __uint_as_float(~(unsigned)(s_key[tid] >> 32));
        g_maskedT[cls * N_OBJn + o] = keep ? sc : 0.0f;
    }
}

// ---------------------------------------------------------------------------
// Kernel 3: argmax, one WARP per object (first-max tie: smaller class wins)
// ---------------------------------------------------------------------------
__global__ void argmax_kernel(float* __restrict__ out)
{
    int wid  = threadIdx.x >> 5;
    int lane = threadIdx.x & 31;
    int obj  = blockIdx.x * 8 + wid;
    if (obj >= N_OBJn) return;

    float bv = -1.0f;
    int   bc = 1000;
#pragma unroll
    for (int s = 0; s < 5; s++) {
        int c = 1 + lane + 32 * s;
        if (c < C_OBJn) {
            float v = g_maskedT[c * N_OBJn + obj];
            if (v > bv || (v == bv && c < bc)) { bv = v; bc = c; }
        }
    }
#pragma unroll
    for (int o = 16; o; o >>= 1) {
        float ov = __shfl_xor_sync(0xffffffffu, bv, o);
        int   oc = __shfl_xor_sync(0xffffffffu, bc, o);
        if (ov > bv || (ov == bv && oc < bc)) { bv = ov; bc = oc; }
    }
    if (lane == 0) out[OUT_PREDS + obj] = (float)bc;
}

// ---------------------------------------------------------------------------
// Kernel 4a: W[51,4096] fp32 -> fp16, padded to 64 rows
// ---------------------------------------------------------------------------
__global__ void wsplit_kernel(const float* __restrict__ W)
{
    int i = blockIdx.x * blockDim.x + threadIdx.x;
    if (i >= 64 * D_DIM) return;
    int n = i >> 12;
    float x = (n < C_RELn) ? W[i] : 0.0f;
    g_Whf[i] = __float2half_rn(x);
}

// ---------------------------------------------------------------------------
// Kernel 4b: fp16 2-product split GEMM via mma.sync (UNCHANGED: 74us measured)
// ---------------------------------------------------------------------------
#define OFF_AHI 0
#define OFF_ALO 8192
#define OFF_WHF 16384
#define BUFSZ   24576
#define SM_TOTAL (2 * BUFSZ)

__device__ __forceinline__ uint32_t pkh2(__half a, __half b) {
    __half2 t = __halves2half2(a, b);
    return *(uint32_t*)&t;
}

__global__ __launch_bounds__(256, 2) void gemm_tc_kernel(const float* __restrict__ A,
                                                         const float* __restrict__ bias,
                                                         float* __restrict__ out)
{
    extern __shared__ char smem[];
    const uint32_t sb = smem_u32(smem);
    const int tid  = threadIdx.x;
    const int lane = tid & 31;
    const int wid  = tid >> 5;
    const int warp_m = wid & 3;
    const int warp_n = wid >> 2;
    const int rowBase = blockIdx.x * 64;

    const int ar = tid >> 4;
    const int aq = tid & 15;
    const float* aPtr = A + (size_t)(rowBase + ar) * D_DIM + aq * 4;

    float4 ra[4];
    uint4  rw[2];

    auto ldg = [&](int k0) {
#pragma unroll
        for (int p = 0; p < 4; p++)
            ra[p] = *(const float4*)(aPtr + (size_t)16 * p * D_DIM + k0);
#pragma unroll
        for (int u = 0; u < 2; u++) {
            int idx = tid * 2 + u;
            int n = idx >> 3, q = idx & 7;
            rw[u] = *(const uint4*)&g_Whf[(size_t)n * D_DIM + k0 + q * 8];
        }
    };

    auto sts = [&](int buf) {
        char* bp = smem + buf * BUFSZ;
#pragma unroll
        for (int p = 0; p < 4; p++) {
            int r = ar + 16 * p;
            uint32_t off = SW128((uint32_t)(r * 128 + aq * 8));
            float v0 = ra[p].x, v1 = ra[p].y, v2 = ra[p].z, v3 = ra[p].w;
            __half h0 = __float2half_rn(v0), h1 = __float2half_rn(v1);
            __half h2 = __float2half_rn(v2), h3 = __float2half_rn(v3);
            __half l0 = __float2half_rn(v0 - __half2float(h0));
            __half l1 = __float2half_rn(v1 - __half2float(h1));
            __half l2 = __float2half_rn(v2 - __half2float(h2));
            __half l3 = __float2half_rn(v3 - __half2float(h3));
            *(uint2*)(bp + OFF_AHI + off) = make_uint2(pkh2(h0, h1), pkh2(h2, h3));
            *(uint2*)(bp + OFF_ALO + off) = make_uint2(pkh2(l0, l1), pkh2(l2, l3));
        }
#pragma unroll
        for (int u = 0; u < 2; u++) {
            int idx = tid * 2 + u;
            int n = idx >> 3, q = idx & 7;
            uint32_t off = SW128((uint32_t)(n * 128 + q * 16));
            *(uint4*)(bp + OFF_WHF + off) = rw[u];
        }
    };

    float accH[4][4], accL[4][4];
#pragma unroll
    for (int nt = 0; nt < 4; nt++)
#pragma unroll
        for (int e = 0; e < 4; e++) { accH[nt][e] = 0.f; accL[nt][e] = 0.f; }

    const uint32_t aRow = (uint32_t)(warp_m * 16 + (lane & 15)) * 128 + (uint32_t)(lane >> 4) * 16;
    const uint32_t bRow = (uint32_t)(warp_n * 32 + ((lane >> 4) & 1) * 8 + (lane & 7)) * 128 +
                          (uint32_t)((lane >> 3) & 1) * 16;

    ldg(0);
    sts(0);
    __syncthreads();

#pragma unroll 1
    for (int i = 0; i < 64; i++) {
        if (i < 63) ldg((i + 1) * 64);

        const uint32_t bb = sb + (uint32_t)(i & 1) * BUFSZ;
#pragma unroll
        for (int kk = 0; kk < 4; kk++) {
            uint32_t aH[4], aL[4], bW[2][4];
            {
                uint32_t o = SW128(aRow + (uint32_t)kk * 32);
                ldmx4(aH, bb + OFF_AHI + o);
                ldmx4(aL, bb + OFF_ALO + o);
            }
#pragma unroll
            for (int pr = 0; pr < 2; pr++) {
                uint32_t o = SW128(bRow + (uint32_t)pr * 2048 + (uint32_t)kk * 32);
                ldmx4(bW[pr], bb + OFF_WHF + o);
            }
#pragma unroll
            for (int nt = 0; nt < 4; nt++) {
                const uint32_t* bw = &bW[nt >> 1][(nt & 1) * 2];
                mma_f16(accH[nt], aH, bw);
                mma_f16(accL[nt], aL, bw);
            }
        }

        if (i < 63) {
            sts((i + 1) & 1);
            __syncthreads();
        }
    }

    const int g  = lane >> 2;
    const int tg = lane & 3;
    int row0 = rowBase + warp_m * 16 + g;
#pragma unroll
    for (int nt = 0; nt < 4; nt++) {
        int col = warp_n * 32 + nt * 8 + tg * 2;
        if (col < C_RELn) {
            float b0 = bias[col];
            out[OUT_REL + (size_t)row0 * C_RELn + col]       = accH[nt][0] + accL[nt][0] + b0;
            out[OUT_REL + (size_t)(row0 + 8) * C_RELn + col] = accH[nt][2] + accL[nt][2] + b0;
        }
        if (col + 1 < C_RELn) {
            float b1 = bias[col + 1];
            out[OUT_REL + (size_t)row0 * C_RELn + col + 1]       = accH[nt][1] + accL[nt][1] + b1;
            out[OUT_REL + (size_t)(row0 + 8) * C_RELn + col + 1] = accH[nt][3] + accL[nt][3] + b1;
        }
    }
}

// ---------------------------------------------------------------------------
// Serial pipeline; nms at issue position 3 so ncu profiles the change.
// ---------------------------------------------------------------------------
extern "C" void kernel_launch(void* const* d_in, const int* in_sizes, int n_in,
                              void* d_out, int out_size)
{
    (void)in_sizes; (void)n_in; (void)out_size;
    const float* obj_logits = (const float*)d_in[0];
    const float* vr         = (const float*)d_in[1];
    const float* boxes      = (const float*)d_in[2];
    const float* W_vr       = (const float*)d_in[3];
    const float* b_vr       = (const float*)d_in[4];
    float* out = (float*)d_out;

    cudaFuncSetAttribute(gemm_tc_kernel, cudaFuncAttributeMaxDynamicSharedMemorySize, SM_TOTAL);

    wsplit_kernel<<<512, 512>>>(W_vr);                               // pos 0
    softmax_copy_kernel<<<64, 256>>>(obj_logits, out);               // pos 1
    gemm_tc_kernel<<<N_RELn / 64, 256, SM_TOTAL>>>(vr, b_vr, out);   // pos 2
    nms_kernel<<<150, 512>>>(boxes);                                 // pos 3
    argmax_kernel<<<64, 256>>>(out);                                 // pos 4
}

// round 10
// speedup vs baseline: 2.8437x; 1.0294x over previous
#include <cuda_runtime.h>
#include <cuda_fp16.h>
#include <cstdint>

#define N_OBJn 512
#define C_OBJn 151
#define N_RELn 16384
#define C_RELn 51
#define D_DIM  4096

#define OUT_PREDS  (N_OBJn * C_OBJn)          /* 77312 */
#define OUT_REL    (OUT_PREDS + N_OBJn)       /* 77824 */

// Scratch (device globals — no allocation allowed)
__device__ float g_probsT[C_OBJn * N_OBJn];   // [class][obj]
__device__ float g_maskedT[C_OBJn * N_OBJn];  // [class][obj], class 0 unused
__device__ __align__(16) __half g_Whf[64 * D_DIM];  // W as fp16, rows 51..63 zero

// ---------------------------------------------------------------------------
// helpers
// ---------------------------------------------------------------------------
__device__ __forceinline__ uint32_t smem_u32(const void* p) {
    uint32_t a;
    asm("{ .reg .u64 t; cvta.to.shared.u64 t, %1; cvt.u32.u64 %0, t; }" : "=r"(a) : "l"(p));
    return a;
}
#define SW128(o) ((o) ^ (((o) >> 3) & 0x70))

__device__ __forceinline__ void ldmx4(uint32_t* r, uint32_t addr) {
    asm volatile("ldmatrix.sync.aligned.m8n8.x4.shared.b16 {%0,%1,%2,%3}, [%4];"
                 : "=r"(r[0]), "=r"(r[1]), "=r"(r[2]), "=r"(r[3]) : "r"(addr));
}
__device__ __forceinline__ void mma_f16(float* d, const uint32_t* a, const uint32_t* b) {
    asm volatile(
        "mma.sync.aligned.m16n8k16.row.col.f32.f16.f16.f32 "
        "{%0,%1,%2,%3},{%4,%5,%6,%7},{%8,%9},{%0,%1,%2,%3};"
        : "+f"(d[0]), "+f"(d[1]), "+f"(d[2]), "+f"(d[3])
        : "r"(a[0]), "r"(a[1]), "r"(a[2]), "r"(a[3]), "r"(b[0]), "r"(b[1]));
}

// Exact IoU>0.3 predicate, division-free fast path (proven r9, byte-identical).
__device__ __forceinline__ bool iou_gt(float inter, float den) {
    float t    = __fmul_rn(0.3f, den);
    float diff = __fsub_rn(inter, t);
    bool pred  = diff > 0.0f;
    if (fabsf(diff) < __fmul_rn(t, 4e-7f))
        pred = __fdiv_rn(inter, den) > 0.3f;
    return pred;
}

__device__ __forceinline__ float iou_inter(const float4& a, const float4& b) {
    float xx1 = fmaxf(a.x, b.x);
    float yy1 = fmaxf(a.y, b.y);
    float xx2 = fminf(a.z, b.z);
    float yy2 = fminf(a.w, b.w);
    float wd = fmaxf(__fadd_rn(__fsub_rn(xx2, xx1), 1.0f), 0.0f);
    float ht = fmaxf(__fadd_rn(__fsub_rn(yy2, yy1), 1.0f), 0.0f);
    return __fmul_rn(wd, ht);
}

// ---------------------------------------------------------------------------
// Kernel 1: row softmax (one warp per row) + copy logits to out[0:77312)
// ---------------------------------------------------------------------------
__global__ void softmax_copy_kernel(const float* __restrict__ logits,
                                    float* __restrict__ out)
{
    int warp = threadIdx.x >> 5;
    int lane = threadIdx.x & 31;
    int row  = blockIdx.x * 8 + warp;
    if (row >= N_OBJn) return;

    float v[5];
    float mx = -1e30f;
#pragma unroll
    for (int s = 0; s < 5; s++) {
        int c = lane + 32 * s;
        v[s] = (c < C_OBJn) ? logits[row * C_OBJn + c] : -1e30f;
        mx = fmaxf(mx, v[s]);
    }
#pragma unroll
    for (int o = 16; o; o >>= 1) mx = fmaxf(mx, __shfl_xor_sync(0xffffffffu, mx, o));

    float e[5];
    float sum = 0.f;
#pragma unroll
    for (int s = 0; s < 5; s++) {
        int c = lane + 32 * s;
        e[s] = (c < C_OBJn) ? expf(v[s] - mx) : 0.f;
        sum += e[s];
    }
#pragma unroll
    for (int o = 16; o; o >>= 1) sum += __shfl_xor_sync(0xffffffffu, sum, o);

#pragma unroll
    for (int s = 0; s < 5; s++) {
        int c = lane + 32 * s;
        if (c < C_OBJn) {
            g_probsT[c * N_OBJn + row] = __fdiv_rn(e[s], sum);
            out[row * C_OBJn + c] = v[s];   // obj_dists2 passthrough
        }
    }
}

// ---------------------------------------------------------------------------
// Kernel 2: per-class NMS — lazy block-greedy, division-free predicate,
// + early-exit for already-suppressed columns (supbit monotone => identical
// output), s_sup written only at the block actually read (B == w-1).
// ---------------------------------------------------------------------------
__global__ __launch_bounds__(512) void nms_kernel(const float* __restrict__ boxes)
{
    __shared__ unsigned long long s_key[512];
    __shared__ float4 s_box[512];
    __shared__ float  s_ar[512];
    __shared__ unsigned s_diag[32];
    __shared__ unsigned s_sup[16];
    __shared__ unsigned s_keep[16];

    const int tid  = threadIdx.x;
    const int lane = tid & 31;
    const int w    = tid >> 5;              // 16 warps
    const int cls  = blockIdx.x + 1;

    {
        unsigned sb = __float_as_uint(g_probsT[cls * N_OBJn + tid]);  // probs >= 0
        s_key[tid] = ((unsigned long long)(~sb) << 32) | (unsigned)tid;
    }
    if (tid < 16) s_sup[tid] = 0u;
    __syncthreads();

    // Ascending bitonic sort of 512 u64 keys  == score desc, idx asc
    for (int k = 2; k <= 512; k <<= 1) {
        for (int j = k >> 1; j > 0; j >>= 1) {
            int ixj = tid ^ j;
            if (ixj > tid) {
                unsigned long long a = s_key[tid], b = s_key[ixj];
                bool up = ((tid & k) == 0);
                if ((a > b) == up) { s_key[tid] = b; s_key[ixj] = a; }
            }
            __syncthreads();
        }
    }

    // Load boxes in sorted order; own column box stays in registers
    float4 cb;
    float  ca;
    {
        int o = (int)(s_key[tid] & 0x1FFu);
        cb = *(const float4*)&boxes[(o * C_OBJn + cls) * 4];
        ca = __fmul_rn(__fadd_rn(__fsub_rn(cb.z, cb.x), 1.0f),
                       __fadd_rn(__fsub_rn(cb.w, cb.y), 1.0f));
        s_box[tid] = cb;
        s_ar[tid]  = ca;
    }
    __syncthreads();

    unsigned supbit = 0;   // this thread's column suppressed-so-far flag

#pragma unroll 1
    for (int B = 0; B < 16; B++) {
        // (1) diag block: warp w computes rows 2w, 2w+1; col box hoisted per B
        {
            float4 db = s_box[(B << 5) + lane];
            float  da = s_ar[(B << 5) + lane];
#pragma unroll
            for (int rr = 0; rr < 2; rr++) {
                int r = (B << 5) + (w << 1) + rr;
                float4 rb = s_box[r];
                float  ra = s_ar[r];
                float inter = iou_inter(rb, db);
                float den = __fsub_rn(__fadd_rn(ra, da), inter);
                unsigned m = __ballot_sync(0xffffffffu, iou_gt(inter, den));
                if (lane == 0) s_diag[(w << 1) + rr] = m;
            }
        }
        __syncthreads();

        // (2) keep-chain, redundant per warp (pure ALU, fully unrolled)
        unsigned cur = s_sup[B];
        unsigned kb  = 0;
#pragma unroll
        for (int t = 0; t < 32; t++) {
            unsigned mi   = s_diag[t];
            unsigned keep = ((cur >> t) & 1u) ^ 1u;
            kb  |= keep << t;
            cur |= keep ? mi : 0u;
        }
        if (tid == 0) s_keep[B] = kb;

        // (3) kept rows of block B suppress future columns (w > B only).
        // Early-exit: a column already suppressed needs no more IoUs.
        if (w > B) {
            if (!supbit) {
                unsigned bits = kb;
                while (bits) {
                    int t = __ffs(bits) - 1;
                    bits &= bits - 1;
                    int i = (B << 5) + t;
                    float4 ib = s_box[i];         // warp-uniform broadcast LDS.128
                    float  ia = s_ar[i];
                    float inter = iou_inter(ib, cb);
                    float den = __fsub_rn(__fadd_rn(ia, ca), inter);
                    if (iou_gt(inter, den)) { supbit = 1u; break; }
                }
            }
            // only the write preceding this warp's read (B == w-1) matters
            unsigned m = __ballot_sync(0xffffffffu, supbit);
            if (lane == 0 && B == w - 1) s_sup[w] = m;
        }
        __syncthreads();
    }

    {
        unsigned kb = s_keep[w];
        bool keep = (kb >> lane) & 1u;
        int o = (int)(s_key[tid] & 0x1FFu);
        float sc = __uint_as_float(~(unsigned)(s_key[tid] >> 32));
        g_maskedT[cls * N_OBJn + o] = keep ? sc : 0.0f;
    }
}

// ---------------------------------------------------------------------------
// Kernel 3: argmax, one WARP per object (first-max tie: smaller class wins)
// ---------------------------------------------------------------------------
__global__ void argmax_kernel(float* __restrict__ out)
{
    int wid  = threadIdx.x >> 5;
    int lane = threadIdx.x & 31;
    int obj  = blockIdx.x * 8 + wid;
    if (obj >= N_OBJn) return;

    float bv = -1.0f;
    int   bc = 1000;
#pragma unroll
    for (int s = 0; s < 5; s++) {
        int c = 1 + lane + 32 * s;
        if (c < C_OBJn) {
            float v = g_maskedT[c * N_OBJn + obj];
            if (v > bv || (v == bv && c < bc)) { bv = v; bc = c; }
        }
    }
#pragma unroll
    for (int o = 16; o; o >>= 1) {
        float ov = __shfl_xor_sync(0xffffffffu, bv, o);
        int   oc = __shfl_xor_sync(0xffffffffu, bc, o);
        if (ov > bv || (ov == bv && oc < bc)) { bv = ov; bc = oc; }
    }
    if (lane == 0) out[OUT_PREDS + obj] = (float)bc;
}

// ---------------------------------------------------------------------------
// Kernel 4a: W[51,4096] fp32 -> fp16, padded to 64 rows
// ---------------------------------------------------------------------------
__global__ void wsplit_kernel(const float* __restrict__ W)
{
    int i = blockIdx.x * blockDim.x + threadIdx.x;
    if (i >= 64 * D_DIM) return;
    int n = i >> 12;
    float x = (n < C_RELn) ? W[i] : 0.0f;
    g_Whf[i] = __float2half_rn(x);
}

// ---------------------------------------------------------------------------
// Kernel 4b: SINGLE-product fp16 GEMM via mma.sync.
// A and W both fp16-rounded: independent ~2^-12-scale errors over K=4096
// => rel_err ~= sqrt(2)*2.08e-4 ~= 3e-4, 3.4x under the 1e-3 gate.
// Halves HMMA count, A smem, conversion and ldmatrix work vs 2-product.
// ---------------------------------------------------------------------------
#define OFF_AHF 0
#define OFF_WHF 8192
#define BUFSZ   16384
#define SM_TOTAL (2 * BUFSZ)

__global__ __launch_bounds__(256, 2) void gemm_tc_kernel(const float* __restrict__ A,
                                                         const float* __restrict__ bias,
                                                         float* __restrict__ out)
{
    extern __shared__ char smem[];
    const uint32_t sb = smem_u32(smem);
    const int tid  = threadIdx.x;
    const int lane = tid & 31;
    const int wid  = tid >> 5;
    const int warp_m = wid & 3;
    const int warp_n = wid >> 2;
    const int rowBase = blockIdx.x * 64;

    const int ar = tid >> 4;
    const int aq = tid & 15;
    const float* aPtr = A + (size_t)(rowBase + ar) * D_DIM + aq * 4;

    float4 ra[4];
    uint4  rw[2];

    auto ldg = [&](int k0) {
#pragma unroll
        for (int p = 0; p < 4; p++)
            ra[p] = *(const float4*)(aPtr + (size_t)16 * p * D_DIM + k0);
#pragma unroll
        for (int u = 0; u < 2; u++) {
            int idx = tid * 2 + u;
            int n = idx >> 3, q = idx & 7;
            rw[u] = *(const uint4*)&g_Whf[(size_t)n * D_DIM + k0 + q * 8];
        }
    };

    auto sts = [&](int buf) {
        char* bp = smem + buf * BUFSZ;
#pragma unroll
        for (int p = 0; p < 4; p++) {
            int r = ar + 16 * p;
            uint32_t off = SW128((uint32_t)(r * 128 + aq * 8));
            __half2 h01 = __floats2half2_rn(ra[p].x, ra[p].y);
            __half2 h23 = __floats2half2_rn(ra[p].z, ra[p].w);
            *(uint2*)(bp + OFF_AHF + off) =
                make_uint2(*(uint32_t*)&h01, *(uint32_t*)&h23);
        }
#pragma unroll
        for (int u = 0; u < 2; u++) {
            int idx = tid * 2 + u;
            int n = idx >> 3, q = idx & 7;
            uint32_t off = SW128((uint32_t)(n * 128 + q * 16));
            *(uint4*)(bp + OFF_WHF + off) = rw[u];
        }
    };

    float acc[4][4];
#pragma unroll
    for (int nt = 0; nt < 4; nt++)
#pragma unroll
        for (int e = 0; e < 4; e++) acc[nt][e] = 0.f;

    const uint32_t aRow = (uint32_t)(warp_m * 16 + (lane & 15)) * 128 + (uint32_t)(lane >> 4) * 16;
    const uint32_t bRow = (uint32_t)(warp_n * 32 + ((lane >> 4) & 1) * 8 + (lane & 7)) * 128 +
                          (uint32_t)((lane >> 3) & 1) * 16;

    ldg(0);
    sts(0);
    __syncthreads();

#pragma unroll 1
    for (int i = 0; i < 64; i++) {
        if (i < 63) ldg((i + 1) * 64);

        const uint32_t bb = sb + (uint32_t)(i & 1) * BUFSZ;
#pragma unroll
        for (int kk = 0; kk < 4; kk++) {
            uint32_t aH[4], bW[2][4];
            {
                uint32_t o = SW128(aRow + (uint32_t)kk * 32);
                ldmx4(aH, bb + OFF_AHF + o);
            }
#pragma unroll
            for (int pr = 0; pr < 2; pr++) {
                uint32_t o = SW128(bRow + (uint32_t)pr * 2048 + (uint32_t)kk * 32);
                ldmx4(bW[pr], bb + OFF_WHF + o);
            }
#pragma unroll
            for (int nt = 0; nt < 4; nt++)
                mma_f16(acc[nt], aH, &bW[nt >> 1][(nt & 1) * 2]);
        }

        if (i < 63) {
            sts((i + 1) & 1);
            __syncthreads();
        }
    }

    const int g  = lane >> 2;
    const int tg = lane & 3;
    int row0 = rowBase + warp_m * 16 + g;
#pragma unroll
    for (int nt = 0; nt < 4; nt++) {
        int col = warp_n * 32 + nt * 8 + tg * 2;
        if (col < C_RELn) {
            float b0 = bias[col];
            out[OUT_REL + (size_t)row0 * C_RELn + col]       = acc[nt][0] + b0;
            out[OUT_REL + (size_t)(row0 + 8) * C_RELn + col] = acc[nt][2] + b0;
        }
        if (col + 1 < C_RELn) {
            float b1 = bias[col + 1];
            out[OUT_REL + (size_t)row0 * C_RELn + col + 1]       = acc[nt][1] + b1;
            out[OUT_REL + (size_t)(row0 + 8) * C_RELn + col + 1] = acc[nt][3] + b1;
        }
    }
}

// ---------------------------------------------------------------------------
// Serial pipeline; GEMM at issue position 3 so ncu verifies the HMMA theory.
// ---------------------------------------------------------------------------
extern "C" void kernel_launch(void* const* d_in, const int* in_sizes, int n_in,
                              void* d_out, int out_size)
{
    (void)in_sizes; (void)n_in; (void)out_size;
    const float* obj_logits = (const float*)d_in[0];
    const float* vr         = (const float*)d_in[1];
    const float* boxes      = (const float*)d_in[2];
    const float* W_vr       = (const float*)d_in[3];
    const float* b_vr       = (const float*)d_in[4];
    float* out = (float*)d_out;

    cudaFuncSetAttribute(gemm_tc_kernel, cudaFuncAttributeMaxDynamicSharedMemorySize, SM_TOTAL);

    wsplit_kernel<<<512, 512>>>(W_vr);                               // pos 0
    softmax_copy_kernel<<<64, 256>>>(obj_logits, out);               // pos 1
    nms_kernel<<<150, 512>>>(boxes);                                 // pos 2
    gemm_tc_kernel<<<N_RELn / 64, 256, SM_TOTAL>>>(vr, b_vr, out);   // pos 3
    argmax_kernel<<<64, 256>>>(out);                                 // pos 4
}

// round 11
// speedup vs baseline: 2.9388x; 1.0335x over previous
#include <cuda_runtime.h>
#include <cuda_fp16.h>
#include <cstdint>

#define N_OBJn 512
#define C_OBJn 151
#define N_RELn 16384
#define C_RELn 51
#define D_DIM  4096

#define OUT_PREDS  (N_OBJn * C_OBJn)          /* 77312 */
#define OUT_REL    (OUT_PREDS + N_OBJn)       /* 77824 */

// Scratch (device globals — no allocation allowed)
__device__ float g_probsT[C_OBJn * N_OBJn];   // [class][obj]
__device__ float g_maskedT[C_OBJn * N_OBJn];  // [class][obj], class 0 unused
// W as fp16, pre-swizzled per 64-col chunk tile: 64 tiles x (64 rows x 128B)
__device__ __align__(16) unsigned char g_Wsw[64 * 8192];

// ---------------------------------------------------------------------------
// helpers
// ---------------------------------------------------------------------------
__device__ __forceinline__ uint32_t smem_u32(const void* p) {
    uint32_t a;
    asm("{ .reg .u64 t; cvta.to.shared.u64 t, %1; cvt.u32.u64 %0, t; }" : "=r"(a) : "l"(p));
    return a;
}
#define SW128(o) ((o) ^ (((o) >> 3) & 0x70))

__device__ __forceinline__ void cp_async16(uint32_t dst, const void* src) {
    asm volatile("cp.async.cg.shared.global [%0], [%1], 16;" :: "r"(dst), "l"(src));
}
#define CP_COMMIT() asm volatile("cp.async.commit_group;")
#define CP_WAIT2()  asm volatile("cp.async.wait_group 2;")

__device__ __forceinline__ void ldmx4(uint32_t* r, uint32_t addr) {
    asm volatile("ldmatrix.sync.aligned.m8n8.x4.shared.b16 {%0,%1,%2,%3}, [%4];"
                 : "=r"(r[0]), "=r"(r[1]), "=r"(r[2]), "=r"(r[3]) : "r"(addr));
}
__device__ __forceinline__ void mma_f16(float* d, const uint32_t* a, const uint32_t* b) {
    asm volatile(
        "mma.sync.aligned.m16n8k16.row.col.f32.f16.f16.f32 "
        "{%0,%1,%2,%3},{%4,%5,%6,%7},{%8,%9},{%0,%1,%2,%3};"
        : "+f"(d[0]), "+f"(d[1]), "+f"(d[2]), "+f"(d[3])
        : "r"(a[0]), "r"(a[1]), "r"(a[2]), "r"(a[3]), "r"(b[0]), "r"(b[1]));
}

// Exact IoU>0.3 predicate, division-free fast path (proven r9, byte-identical).
__device__ __forceinline__ bool iou_gt(float inter, float den) {
    float t    = __fmul_rn(0.3f, den);
    float diff = __fsub_rn(inter, t);
    bool pred  = diff > 0.0f;
    if (fabsf(diff) < __fmul_rn(t, 4e-7f))
        pred = __fdiv_rn(inter, den) > 0.3f;
    return pred;
}

__device__ __forceinline__ float iou_inter(const float4& a, const float4& b) {
    float xx1 = fmaxf(a.x, b.x);
    float yy1 = fmaxf(a.y, b.y);
    float xx2 = fminf(a.z, b.z);
    float yy2 = fminf(a.w, b.w);
    float wd = fmaxf(__fadd_rn(__fsub_rn(xx2, xx1), 1.0f), 0.0f);
    float ht = fmaxf(__fadd_rn(__fsub_rn(yy2, yy1), 1.0f), 0.0f);
    return __fmul_rn(wd, ht);
}

// ---------------------------------------------------------------------------
// Kernel 1: row softmax (one warp per row) + copy logits to out[0:77312)
// ---------------------------------------------------------------------------
__global__ void softmax_copy_kernel(const float* __restrict__ logits,
                                    float* __restrict__ out)
{
    int warp = threadIdx.x >> 5;
    int lane = threadIdx.x & 31;
    int row  = blockIdx.x * 8 + warp;
    if (row >= N_OBJn) return;

    float v[5];
    float mx = -1e30f;
#pragma unroll
    for (int s = 0; s < 5; s++) {
        int c = lane + 32 * s;
        v[s] = (c < C_OBJn) ? logits[row * C_OBJn + c] : -1e30f;
        mx = fmaxf(mx, v[s]);
    }
#pragma unroll
    for (int o = 16; o; o >>= 1) mx = fmaxf(mx, __shfl_xor_sync(0xffffffffu, mx, o));

    float e[5];
    float sum = 0.f;
#pragma unroll
    for (int s = 0; s < 5; s++) {
        int c = lane + 32 * s;
        e[s] = (c < C_OBJn) ? expf(v[s] - mx) : 0.f;
        sum += e[s];
    }
#pragma unroll
    for (int o = 16; o; o >>= 1) sum += __shfl_xor_sync(0xffffffffu, sum, o);

#pragma unroll
    for (int s = 0; s < 5; s++) {
        int c = lane + 32 * s;
        if (c < C_OBJn) {
            g_probsT[c * N_OBJn + row] = __fdiv_rn(e[s], sum);
            out[row * C_OBJn + c] = v[s];   // obj_dists2 passthrough
        }
    }
}

// ---------------------------------------------------------------------------
// Kernel 2: per-class NMS (unchanged from r10: 49us measured, early-exit)
// ---------------------------------------------------------------------------
__global__ __launch_bounds__(512) void nms_kernel(const float* __restrict__ boxes)
{
    __shared__ unsigned long long s_key[512];
    __shared__ float4 s_box[512];
    __shared__ float  s_ar[512];
    __shared__ unsigned s_diag[32];
    __shared__ unsigned s_sup[16];
    __shared__ unsigned s_keep[16];

    const int tid  = threadIdx.x;
    const int lane = tid & 31;
    const int w    = tid >> 5;              // 16 warps
    const int cls  = blockIdx.x + 1;

    {
        unsigned sb = __float_as_uint(g_probsT[cls * N_OBJn + tid]);  // probs >= 0
        s_key[tid] = ((unsigned long long)(~sb) << 32) | (unsigned)tid;
    }
    if (tid < 16) s_sup[tid] = 0u;
    __syncthreads();

    for (int k = 2; k <= 512; k <<= 1) {
        for (int j = k >> 1; j > 0; j >>= 1) {
            int ixj = tid ^ j;
            if (ixj > tid) {
                unsigned long long a = s_key[tid], b = s_key[ixj];
                bool up = ((tid & k) == 0);
                if ((a > b) == up) { s_key[tid] = b; s_key[ixj] = a; }
            }
            __syncthreads();
        }
    }

    float4 cb;
    float  ca;
    {
        int o = (int)(s_key[tid] & 0x1FFu);
        cb = *(const float4*)&boxes[(o * C_OBJn + cls) * 4];
        ca = __fmul_rn(__fadd_rn(__fsub_rn(cb.z, cb.x), 1.0f),
                       __fadd_rn(__fsub_rn(cb.w, cb.y), 1.0f));
        s_box[tid] = cb;
        s_ar[tid]  = ca;
    }
    __syncthreads();

    unsigned supbit = 0;

#pragma unroll 1
    for (int B = 0; B < 16; B++) {
        {
            float4 db = s_box[(B << 5) + lane];
            float  da = s_ar[(B << 5) + lane];
#pragma unroll
            for (int rr = 0; rr < 2; rr++) {
                int r = (B << 5) + (w << 1) + rr;
                float4 rb = s_box[r];
                float  ra = s_ar[r];
                float inter = iou_inter(rb, db);
                float den = __fsub_rn(__fadd_rn(ra, da), inter);
                unsigned m = __ballot_sync(0xffffffffu, iou_gt(inter, den));
                if (lane == 0) s_diag[(w << 1) + rr] = m;
            }
        }
        __syncthreads();

        unsigned cur = s_sup[B];
        unsigned kb  = 0;
#pragma unroll
        for (int t = 0; t < 32; t++) {
            unsigned mi   = s_diag[t];
            unsigned keep = ((cur >> t) & 1u) ^ 1u;
            kb  |= keep << t;
            cur |= keep ? mi : 0u;
        }
        if (tid == 0) s_keep[B] = kb;

        if (w > B) {
            if (!supbit) {
                unsigned bits = kb;
                while (bits) {
                    int t = __ffs(bits) - 1;
                    bits &= bits - 1;
                    int i = (B << 5) + t;
                    float4 ib = s_box[i];
                    float  ia = s_ar[i];
                    float inter = iou_inter(ib, cb);
                    float den = __fsub_rn(__fadd_rn(ia, ca), inter);
                    if (iou_gt(inter, den)) { supbit = 1u; break; }
                }
            }
            unsigned m = __ballot_sync(0xffffffffu, supbit);
            if (lane == 0 && B == w - 1) s_sup[w] = m;
        }
        __syncthreads();
    }

    {
        unsigned kb = s_keep[w];
        bool keep = (kb >> lane) & 1u;
        int o = (int)(s_key[tid] & 0x1FFu);
        float sc = __uint_as_float(~(unsigned)(s_key[tid] >> 32));
        g_maskedT[cls * N_OBJn + o] = keep ? sc : 0.0f;
    }
}

// ---------------------------------------------------------------------------
// Kernel 3: argmax, one WARP per object (first-max tie: smaller class wins)
// ---------------------------------------------------------------------------
__global__ void argmax_kernel(float* __restrict__ out)
{
    int wid  = threadIdx.x >> 5;
    int lane = threadIdx.x & 31;
    int obj  = blockIdx.x * 8 + wid;
    if (obj >= N_OBJn) return;

    float bv = -1.0f;
    int   bc = 1000;
#pragma unroll
    for (int s = 0; s < 5; s++) {
        int c = 1 + lane + 32 * s;
        if (c < C_OBJn) {
            float v = g_maskedT[c * N_OBJn + obj];
            if (v > bv || (v == bv && c < bc)) { bv = v; bc = c; }
        }
    }
#pragma unroll
    for (int o = 16; o; o >>= 1) {
        float ov = __shfl_xor_sync(0xffffffffu, bv, o);
        int   oc = __shfl_xor_sync(0xffffffffu, bc, o);
        if (ov > bv || (ov == bv && oc < bc)) { bv = ov; bc = oc; }
    }
    if (lane == 0) out[OUT_PREDS + obj] = (float)bc;
}

// ---------------------------------------------------------------------------
// Kernel 4a: W[51,4096] fp32 -> fp16, PRE-SWIZZLED per-chunk tiles.
// Tile t (k=64t..64t+63): byte (n*128 + kin*2) ^ ((n&7)*16), 8KB contiguous.
// ---------------------------------------------------------------------------
__global__ void wsplit_kernel(const float* __restrict__ W)
{
    int i = blockIdx.x * blockDim.x + threadIdx.x;   // n*4096 + k
    if (i >= 64 * D_DIM) return;
    int n = i >> 12;
    int k = i & 4095;
    float x = (n < C_RELn) ? W[i] : 0.0f;
    __half h = __float2half_rn(x);
    int chunk = k >> 6, kin = k & 63;
    uint32_t off = (uint32_t)(n * 128 + kin * 2);
    uint32_t dst = (uint32_t)chunk * 8192u + (off ^ ((uint32_t)(n & 7) * 16u));
    *(__half*)(g_Wsw + dst) = h;
}

// ---------------------------------------------------------------------------
// Kernel 4b: fp16 GEMM, 3-stage cp.async pipeline.
// Stage = A fp32 (64 rows x 272B) + W fp16 swizzled tile (8KB).
// Per chunk: wait stage -> convert A to swizzled fp16 buf (alt 2) + ldmatrix W
// to regs -> sync -> issue stage i+3 -> ldmatrix A + HMMA.
// Math identical to r10 single-product fp16 (rel_err must stay 2.943e-4).
// ---------------------------------------------------------------------------
#define ASTRIDE 272
#define A_STAGE_B (64 * ASTRIDE)                       /* 17408 */
#define W_STAGE_B 8192
#define STAGE_B   (A_STAGE_B + W_STAGE_B)              /* 25600 */
#define OFF_STA(s) ((s) * STAGE_B)
#define OFF_STW(s) ((s) * STAGE_B + A_STAGE_B)
#define OFF_FB(b)  (3 * STAGE_B + (b) * 8192)
#define SM_TOTAL_G (3 * STAGE_B + 2 * 8192)            /* 93184 */

__global__ __launch_bounds__(256, 2) void gemm_tc_kernel(const float* __restrict__ A,
                                                         const float* __restrict__ bias,
                                                         float* __restrict__ out)
{
    extern __shared__ char smem[];
    const uint32_t sb = smem_u32(smem);
    const int tid  = threadIdx.x;
    const int lane = tid & 31;
    const int wid  = tid >> 5;
    const int warp_m = wid & 3;
    const int warp_n = wid >> 2;
    const int rowBase = blockIdx.x * 64;

    const int ar = tid >> 4;       // base row (0..15), handles ar+16p
    const int aq = tid & 15;       // 16B quad within 256B k-window
    const float* aPtr = A + (size_t)(rowBase + ar) * D_DIM + aq * 4;

    auto issue = [&](int i) {       // one commit_group per call (maybe empty)
        if (i < 64) {
            uint32_t ab = sb + OFF_STA(i % 3);
            const float* ag = aPtr + i * 64;
#pragma unroll
            for (int p = 0; p < 4; p++)
                cp_async16(ab + (uint32_t)(ar + 16 * p) * ASTRIDE + aq * 16,
                           ag + (size_t)16 * p * D_DIM);
            uint32_t wb = sb + OFF_STW(i % 3);
            const unsigned char* wg = g_Wsw + (size_t)i * 8192 + tid * 16;
            cp_async16(wb + tid * 16, wg);
            cp_async16(wb + 4096 + tid * 16, wg + 4096);
        }
        CP_COMMIT();
    };

    float acc[4][4];
#pragma unroll
    for (int nt = 0; nt < 4; nt++)
#pragma unroll
        for (int e = 0; e < 4; e++) acc[nt][e] = 0.f;

    const uint32_t aRow = (uint32_t)(warp_m * 16 + (lane & 15)) * 128 + (uint32_t)(lane >> 4) * 16;
    const uint32_t bRow = (uint32_t)(warp_n * 32 + ((lane >> 4) & 1) * 8 + (lane & 7)) * 128 +
                          (uint32_t)((lane >> 3) & 1) * 16;

    issue(0); issue(1); issue(2);

#pragma unroll 1
    for (int i = 0; i < 64; i++) {
        CP_WAIT2();
        __syncthreads();                 // stage i visible to all

        const int s = i % 3;
        // convert A stage -> fp16 swizzled buffer (i&1)
        {
            const char* ap = smem + OFF_STA(s);
            char* fb = smem + OFF_FB(i & 1);
#pragma unroll
            for (int p = 0; p < 4; p++) {
                int r = ar + 16 * p;
                float4 v = *(const float4*)(ap + r * ASTRIDE + aq * 16);
                __half2 h01 = __floats2half2_rn(v.x, v.y);
                __half2 h23 = __floats2half2_rn(v.z, v.w);
                *(uint2*)(fb + SW128((uint32_t)(r * 128 + aq * 8))) =
                    make_uint2(*(uint32_t*)&h01, *(uint32_t*)&h23);
            }
        }
        // W fragments for the whole chunk into registers
        uint32_t bW[4][2][4];
        {
            uint32_t wb = sb + OFF_STW(s);
#pragma unroll
            for (int kk = 0; kk < 4; kk++)
#pragma unroll
                for (int pr = 0; pr < 2; pr++)
                    ldmx4(bW[kk][pr],
                          wb + SW128(bRow + (uint32_t)pr * 2048 + (uint32_t)kk * 32));
        }
        __syncthreads();                 // fbuf ready; stage fully consumed

        issue(i + 3);                    // refill stage (i%3)

        const uint32_t fb = sb + OFF_FB(i & 1);
#pragma unroll
        for (int kk = 0; kk < 4; kk++) {
            uint32_t aH[4];
            ldmx4(aH, fb + SW128(aRow + (uint32_t)kk * 32));
#pragma unroll
            for (int nt = 0; nt < 4; nt++)
                mma_f16(acc[nt], aH, &bW[kk][nt >> 1][(nt & 1) * 2]);
        }
    }

    const int g  = lane >> 2;
    const int tg = lane & 3;
    int row0 = rowBase + warp_m * 16 + g;
#pragma unroll
    for (int nt = 0; nt < 4; nt++) {
        int col = warp_n * 32 + nt * 8 + tg * 2;
        if (col < C_RELn) {
            float b0 = bias[col];
            out[OUT_REL + (size_t)row0 * C_RELn + col]       = acc[nt][0] + b0;
            out[OUT_REL + (size_t)(row0 + 8) * C_RELn + col] = acc[nt][2] + b0;
        }
        if (col + 1 < C_RELn) {
            float b1 = bias[col + 1];
            out[OUT_REL + (size_t)row0 * C_RELn + col + 1]       = acc[nt][1] + b1;
            out[OUT_REL + (size_t)(row0 + 8) * C_RELn + col + 1] = acc[nt][3] + b1;
        }
    }
}

// ---------------------------------------------------------------------------
// Serial pipeline; GEMM at issue position 3 for ncu.
// ---------------------------------------------------------------------------
extern "C" void kernel_launch(void* const* d_in, const int* in_sizes, int n_in,
                              void* d_out, int out_size)
{
    (void)in_sizes; (void)n_in; (void)out_size;
    const float* obj_logits = (const float*)d_in[0];
    const float* vr         = (const float*)d_in[1];
    const float* boxes      = (const float*)d_in[2];
    const float* W_vr       = (const float*)d_in[3];
    const float* b_vr       = (const float*)d_in[4];
    float* out = (float*)d_out;

    cudaFuncSetAttribute(gemm_tc_kernel, cudaFuncAttributeMaxDynamicSharedMemorySize, SM_TOTAL_G);

    wsplit_kernel<<<512, 512>>>(W_vr);                               // pos 0
    softmax_copy_kernel<<<64, 256>>>(obj_logits, out);               // pos 1
    nms_kernel<<<150, 512>>>(boxes);                                 // pos 2
    gemm_tc_kernel<<<N_RELn / 64, 256, SM_TOTAL_G>>>(vr, b_vr, out); // pos 3
    argmax_kernel<<<64, 256>>>(out);                                 // pos 4
}